// round 11
// baseline (speedup 1.0000x reference)
#include <cuda_runtime.h>
#include <cstdint>

// ---------------------------------------------------------------------------
// PointNet++ (3 SA stages), B=64, N=4096, fp32.
// Round 9: hoist feature-GEMM out of the per-sample gather. For stages 1/2:
//   Y[point] = W_feat @ feats[point] + b   (once per source point)
//   layer0   = relu(W_xyz @ rel_xyz + Y[sample])
// cuts total MACs 7.1G -> 4.6G. Layer1 kernels stay in the proven R6 config.
// ---------------------------------------------------------------------------

static constexpr int B   = 64;
static constexpr int N0  = 4096;
static constexpr int S0  = 128, NSAMP0 = 32;
static constexpr int S1  = 64;
static constexpr int S2  = 32;

// ------------------------- device scratch (no allocs) ----------------------
__device__ float g_nx1[B * S0 * 3];
__device__ float g_nx2[B * S1 * 3];
__device__ float g_nx3[B * S2 * 3];
__device__ int   g_idxbuf[B * S0 * NSAMP0];
__device__ float g_f1[B * S0 * 64];              // stage0 out, (B,S0,64)
__device__ float g_f2[B * S1 * 128];             // stage1 out, (B,S1,128)
__device__ float g_y1[B * S0 * 128];             // stage1 precomputed Y
__device__ float g_y2[B * S1 * 256];             // stage2 precomputed Y

// stage0: k-major folded weights, CIN folded 9->6
__device__ __align__(16) float g_w0T[6 * 32];     __device__ __align__(16) float g_b0[32];
__device__ __align__(16) float g_w1T[32 * 64];    __device__ __align__(16) float g_b1[64];
// stage1: xyz part k-major (3 x 128), feat part o-major (128 x 64)
__device__ __align__(16) float g_w2x[3 * 128];
__device__ __align__(16) float g_w2f[128 * 64];   __device__ __align__(16) float g_b2[128];
__device__ __align__(16) float g_w3T[128 * 128];  __device__ __align__(16) float g_b3[128];
// stage2: xyz part k-major (3 x 256), feat part o-major (256 x 128)
__device__ __align__(16) float g_w4x[3 * 256];
__device__ __align__(16) float g_w4f[256 * 128];  __device__ __align__(16) float g_b4[256];
__device__ __align__(16) float g_w5T[256 * 256];  __device__ __align__(16) float g_b5[256];

// ------------------------- f32x2 helpers -----------------------------------
typedef unsigned long long u64;

__device__ __forceinline__ u64 pack2(float x) {
    u64 r;
    asm("mov.b64 %0, {%1, %2};" : "=l"(r) : "f"(x), "f"(x));
    return r;
}
__device__ __forceinline__ u64 packpair(float lo, float hi) {
    u64 r;
    asm("mov.b64 %0, {%1, %2};" : "=l"(r) : "f"(lo), "f"(hi));
    return r;
}
__device__ __forceinline__ void unpack2(u64 v, float& lo, float& hi) {
    asm("mov.b64 {%0, %1}, %2;" : "=f"(lo), "=f"(hi) : "l"(v));
}
__device__ __forceinline__ u64 ffma2(u64 a, u64 b, u64 c) {
    u64 d;
    asm("fma.rn.f32x2 %0, %1, %2, %3;" : "=l"(d) : "l"(a), "l"(b), "l"(c));
    return d;
}

// ------------------------- merged BN fold ----------------------------------
struct FoldArgs {
    const float* w[6]; const float* g[6]; const float* be[6];
    const float* rm[6]; const float* rv[6];
    float* wT[6];      // k-major dest (l0,l1,l3,l5) or xyz part (l2,l4)
    float* wF[6];      // feat part o-major (l2,l4 only)
    float* bias[6];
    int cin[6]; int cout[6];
};

__global__ void fold_all_kernel(FoldArgs a)
{
    int l = blockIdx.y;
    int cin = a.cin[l], cout = a.cout[l];
    const float* w = a.w[l]; const float* g = a.g[l]; const float* be = a.be[l];
    const float* rm = a.rm[l]; const float* rv = a.rv[l];
    float* wT = a.wT[l]; float* wF = a.wF[l]; float* bias = a.bias[l];
    int i = blockIdx.x * blockDim.x + threadIdx.x;
    if (i < cout) {
        float s = g[i] * rsqrtf(rv[i] + 1e-5f);
        bias[i] = be[i] - s * rm[i];
    }
    if (l == 0) {
        // k-major, fold 9 -> 6 rows (dup abs-xyz)
        int tot = cout * 6;
        for (int e = i; e < tot; e += gridDim.x * blockDim.x) {
            int o = e / 6, k = e - o * 6;
            float s = g[o] * rsqrtf(rv[o] + 1e-5f);
            float val = (k < 3) ? w[o * 9 + k] : (w[o * 9 + k] + w[o * 9 + k + 3]);
            wT[k * cout + o] = val * s;
        }
    } else if (l == 2 || l == 4) {
        // split: k<3 -> xyz k-major; k>=3 -> feat o-major
        int CF = cin - 3;
        int tot = cout * cin;
        for (int e = i; e < tot; e += gridDim.x * blockDim.x) {
            int o = e / cin, k = e - o * cin;
            float s = g[o] * rsqrtf(rv[o] + 1e-5f);
            float val = w[e] * s;
            if (k < 3) wT[k * cout + o] = val;
            else       wF[o * CF + (k - 3)] = val;
        }
    } else {
        // plain k-major
        int tot = cout * cin;
        for (int e = i; e < tot; e += gridDim.x * blockDim.x) {
            int o = e / cin, k = e - o * cin;
            float s = g[o] * rsqrtf(rv[o] + 1e-5f);
            wT[k * cout + o] = w[e] * s;
        }
    }
}

// ------------------------- per-point feature precompute ---------------------
// Y[bp][o] = bias[o] + sum_k wF[o][k] * feats[bp][k].   grid = B*npts, T = C0.
template<int CF, int C0>
__global__ void __launch_bounds__(C0) precompute_kernel(
    const float* __restrict__ feats, const float* __restrict__ wF,
    const float* __restrict__ bias, float* __restrict__ Y)
{
    __shared__ float fs[CF];
    int bp = blockIdx.x;
    const float* f = feats + (size_t)bp * CF;
    for (int i = threadIdx.x; i < CF; i += C0) fs[i] = f[i];
    __syncthreads();
    int o = threadIdx.x;
    float acc = bias[o];
    const float4* wr = reinterpret_cast<const float4*>(wF + (size_t)o * CF);
#pragma unroll 4
    for (int k = 0; k < CF / 4; k++) {
        float4 wv = wr[k];
        acc = fmaf(wv.x, fs[4 * k + 0], acc);
        acc = fmaf(wv.y, fs[4 * k + 1], acc);
        acc = fmaf(wv.z, fs[4 * k + 2], acc);
        acc = fmaf(wv.w, fs[4 * k + 3], acc);
    }
    Y[(size_t)bp * C0 + o] = acc;
}

// ------------------------- farthest point sampling -------------------------
template<int N, int NPOINT, int T>
__global__ void __launch_bounds__(T) fps_kernel(const float* __restrict__ xyz,
                                                float* __restrict__ newxyz)
{
    constexpr int PPT = N / T;
    int b = blockIdx.x;
    int tid = threadIdx.x;
    const float* x = xyz + (size_t)b * N * 3;

    float px[PPT], py[PPT], pz[PPT], dist[PPT];
#pragma unroll
    for (int i = 0; i < PPT; i++) {
        int p = tid + i * T;
        px[i] = x[p * 3 + 0];
        py[i] = x[p * 3 + 1];
        pz[i] = x[p * 3 + 2];
        dist[i] = 1e10f;
    }

    __shared__ float cur[3];
    __shared__ float wv[T / 32];
    __shared__ int   wi[T / 32];

    if (tid == 0) {
        cur[0] = x[0]; cur[1] = x[1]; cur[2] = x[2];
        float* o = newxyz + (size_t)b * NPOINT * 3;
        o[0] = x[0]; o[1] = x[1]; o[2] = x[2];
    }
    __syncthreads();

    for (int j = 1; j < NPOINT; j++) {
        float cx = cur[0], cy = cur[1], cz = cur[2];
        float bv = -1.0f;
        int   bi = 0x7fffffff;
#pragma unroll
        for (int i = 0; i < PPT; i++) {
            float dx = px[i] - cx, dy = py[i] - cy, dz = pz[i] - cz;
            float d = __fadd_rn(__fadd_rn(__fmul_rn(dx, dx), __fmul_rn(dy, dy)),
                                __fmul_rn(dz, dz));
            float nd = fminf(dist[i], d);
            dist[i] = nd;
            int gidx = tid + i * T;
            if (nd > bv || (nd == bv && gidx < bi)) { bv = nd; bi = gidx; }
        }
#pragma unroll
        for (int off = 16; off > 0; off >>= 1) {
            float ov = __shfl_down_sync(0xffffffffu, bv, off);
            int   oi = __shfl_down_sync(0xffffffffu, bi, off);
            if (ov > bv || (ov == bv && oi < bi)) { bv = ov; bi = oi; }
        }
        if ((tid & 31) == 0) { wv[tid >> 5] = bv; wi[tid >> 5] = bi; }
        __syncthreads();
        if (tid < 32) {
            constexpr int NW = T / 32;
            bv = (tid < NW) ? wv[tid] : -2.0f;
            bi = (tid < NW) ? wi[tid] : 0x7fffffff;
#pragma unroll
            for (int off = 16; off > 0; off >>= 1) {
                float ov = __shfl_down_sync(0xffffffffu, bv, off);
                int   oi = __shfl_down_sync(0xffffffffu, bi, off);
                if (ov > bv || (ov == bv && oi < bi)) { bv = ov; bi = oi; }
            }
            if (tid == 0) {
                const float* p = x + (size_t)bi * 3;
                float nx = p[0], ny = p[1], nz = p[2];
                cur[0] = nx; cur[1] = ny; cur[2] = nz;
                float* o = newxyz + ((size_t)b * NPOINT + j) * 3;
                o[0] = nx; o[1] = ny; o[2] = nz;
            }
        }
        __syncthreads();
    }
}

// ------------------------- ball query --------------------------------------
template<int NS>
__global__ void ballquery_kernel(const float* __restrict__ newxyz,
                                 const float* __restrict__ xyz,
                                 int* __restrict__ idxout,
                                 int N, int S, float rr)
{
    __shared__ int rows[4][NS];
    int lane = threadIdx.x & 31;
    int wip  = threadIdx.x >> 5;
    int q = blockIdx.x * 4 + wip;
    int b = q / S;
    const float* nq = newxyz + (size_t)q * 3;
    float qx = nq[0], qy = nq[1], qz = nq[2];
    const float* x = xyz + (size_t)b * N * 3;
    int* row = rows[wip];
    int cnt = 0;

    for (int base = 0; base < N; base += 32) {
        if (cnt >= NS) break;
        int p = base + lane;
        float dx = x[p * 3 + 0] - qx;
        float dy = x[p * 3 + 1] - qy;
        float dz = x[p * 3 + 2] - qz;
        float d = __fadd_rn(__fadd_rn(__fmul_rn(dx, dx), __fmul_rn(dy, dy)),
                            __fmul_rn(dz, dz));
        bool hit = d < rr;
        unsigned m = __ballot_sync(0xffffffffu, hit);
        if (hit) {
            int pos = cnt + __popc(m & ((1u << lane) - 1u));
            if (pos < NS) row[pos] = p;
        }
        cnt += __popc(m);
    }
    __syncwarp();
    int first = (cnt > 0) ? row[0] : 0;
    for (int t = cnt + lane; t < NS; t += 32) row[t] = first;
    __syncwarp();
    for (int t = lane; t < NS; t += 32) idxout[(size_t)q * NS + t] = row[t];
}

// ------------------------- stage0 SIMT MLP ----------------------------------
template<int CIN, int C0, int C1, int NS, int G, int T, int NO0, int NO1>
__global__ void __launch_bounds__(T) sa_mlp0_kernel(
    const float* __restrict__ xyz,
    const float* __restrict__ newxyz, const int* __restrict__ idx,
    const float* __restrict__ w0T, const float* __restrict__ b0,
    const float* __restrict__ w1T, const float* __restrict__ b1,
    float* __restrict__ out, int N, int S)
{
    constexpr int SB = NS * G;
    constexpr int LD = SB + 4;
    constexpr int CQ0 = C0 / 4, NGRP0 = SB / NO0;
    constexpr int CQ1 = C1 / 4, NGRP1 = SB / NO1;
    static_assert(CQ0 * NGRP0 == T, "layer0 mapping");
    static_assert(CQ1 * NGRP1 == T, "layer1 mapping");
    constexpr int OPG = NS / NO1;

    extern __shared__ __align__(16) float smem[];
    float* xs   = smem;
    float* mid  = xs + CIN * LD;
    float* pmax = mid + C0 * LD;

    int gs0 = blockIdx.x * G;
    int b = gs0 / S;
    int tid = threadIdx.x;

    int* sidx = (int*)pmax;
    for (int e = tid; e < SB; e += T)
        sidx[e] = idx[(size_t)(gs0 + e / NS) * NS + (e % NS)];
    __syncthreads();

    for (int e = tid; e < SB; e += T) {
        int g = e / NS;
        int id = sidx[e];
        const float* p = xyz + ((size_t)b * N + id) * 3;
        const float* c = newxyz + (size_t)(gs0 + g) * 3;
        float ax = p[0], ay = p[1], az = p[2];
        xs[0 * LD + e] = ax - c[0];
        xs[1 * LD + e] = ay - c[1];
        xs[2 * LD + e] = az - c[2];
        xs[3 * LD + e] = ax; xs[4 * LD + e] = ay; xs[5 * LD + e] = az;
    }
    __syncthreads();

    {
        int cq = tid % CQ0;
        int n8 = tid / CQ0;
        u64 acc[4][NO0 / 2];
        {
            float4 bv = *reinterpret_cast<const float4*>(b0 + 4 * cq);
            float bk[4] = {bv.x, bv.y, bv.z, bv.w};
#pragma unroll
            for (int i = 0; i < 4; i++) {
                u64 p = pack2(bk[i]);
#pragma unroll
                for (int j = 0; j < NO0 / 2; j++) acc[i][j] = p;
            }
        }
        const float* xrow = xs + n8 * NO0;
        const float* wptr = w0T + 4 * cq;
#pragma unroll 4
        for (int k = 0; k < CIN; k++) {
            float4 w = *reinterpret_cast<const float4*>(wptr + k * C0);
            ulonglong2 v[NO0 / 4];
            const ulonglong2* xr = reinterpret_cast<const ulonglong2*>(xrow + k * LD);
#pragma unroll
            for (int j = 0; j < NO0 / 4; j++) v[j] = xr[j];
            float wk[4] = {w.x, w.y, w.z, w.w};
#pragma unroll
            for (int i = 0; i < 4; i++) {
                u64 w2 = pack2(wk[i]);
#pragma unroll
                for (int j = 0; j < NO0 / 4; j++) {
                    acc[i][2 * j + 0] = ffma2(w2, v[j].x, acc[i][2 * j + 0]);
                    acc[i][2 * j + 1] = ffma2(w2, v[j].y, acc[i][2 * j + 1]);
                }
            }
        }
#pragma unroll
        for (int i = 0; i < 4; i++) {
            float* mrow = mid + (4 * cq + i) * LD + n8 * NO0;
#pragma unroll
            for (int j = 0; j < NO0 / 2; j++) {
                float lo, hi;
                unpack2(acc[i][j], lo, hi);
                float2 r;
                r.x = fmaxf(lo, 0.0f);
                r.y = fmaxf(hi, 0.0f);
                *reinterpret_cast<float2*>(mrow + 2 * j) = r;
            }
        }
    }
    __syncthreads();

    {
        int cq = tid % CQ1;
        int n8 = tid / CQ1;
        u64 acc[4][NO1 / 2];
        {
            float4 bv = *reinterpret_cast<const float4*>(b1 + 4 * cq);
            float bk[4] = {bv.x, bv.y, bv.z, bv.w};
#pragma unroll
            for (int i = 0; i < 4; i++) {
                u64 p = pack2(bk[i]);
#pragma unroll
                for (int j = 0; j < NO1 / 2; j++) acc[i][j] = p;
            }
        }
        const float* mrowb = mid + n8 * NO1;
        const float* wptr = w1T + 4 * cq;
#pragma unroll 4
        for (int k = 0; k < C0; k++) {
            float4 w = *reinterpret_cast<const float4*>(wptr + k * C1);
            ulonglong2 v[NO1 / 4];
            const ulonglong2* mr = reinterpret_cast<const ulonglong2*>(mrowb + k * LD);
#pragma unroll
            for (int j = 0; j < NO1 / 4; j++) v[j] = mr[j];
            float wk[4] = {w.x, w.y, w.z, w.w};
#pragma unroll
            for (int i = 0; i < 4; i++) {
                u64 w2 = pack2(wk[i]);
#pragma unroll
                for (int j = 0; j < NO1 / 4; j++) {
                    acc[i][2 * j + 0] = ffma2(w2, v[j].x, acc[i][2 * j + 0]);
                    acc[i][2 * j + 1] = ffma2(w2, v[j].y, acc[i][2 * j + 1]);
                }
            }
        }
#pragma unroll
        for (int i = 0; i < 4; i++) {
            float m = -3.4e38f;
#pragma unroll
            for (int j = 0; j < NO1 / 2; j++) {
                float lo, hi;
                unpack2(acc[i][j], lo, hi);
                m = fmaxf(m, fmaxf(lo, hi));
            }
            pmax[n8 * C1 + 4 * cq + i] = m;
        }
    }
    __syncthreads();

    for (int e = tid; e < G * C1; e += T) {
        int g = e / C1, ch = e - g * C1;
        float m = pmax[(g * OPG) * C1 + ch];
#pragma unroll
        for (int j = 1; j < OPG; j++)
            m = fmaxf(m, pmax[(g * OPG + j) * C1 + ch]);
        m = fmaxf(m, 0.0f);
        int gs = gs0 + g;
        out[(size_t)gs * C1 + ch] = m;                      // (B, S, C)
    }
}

// ------------------------- stage1/2 SIMT MLP with precomputed Y -------------
// layer0 = relu(W_xyz(3 x C0) @ rel_xyz + Y[sample]); layer1 as before.
template<int C0, int C1, int NS, int T, int NO0, int NO1, bool FINAL>
__global__ void __launch_bounds__(T) sa12_kernel(
    const float* __restrict__ xyz, const float* __restrict__ Y,
    const float* __restrict__ newxyz, const int* __restrict__ idx,
    const float* __restrict__ w0x,
    const float* __restrict__ w1T, const float* __restrict__ b1,
    float* __restrict__ out, int N, int S)
{
    constexpr int LD = NS + 4;
    constexpr int CQ0 = C0 / 4, NGRP0 = NS / NO0;
    constexpr int CQ1 = C1 / 4, NGRP1 = NS / NO1;
    static_assert(CQ0 * NGRP0 == T, "layer0 mapping");
    static_assert(CQ1 * NGRP1 == T, "layer1 mapping");

    extern __shared__ __align__(16) float smem[];
    float* xs   = smem;                 // 3 * LD
    float* mid  = xs + 3 * LD;          // C0 * LD
    float* pmax = mid + C0 * LD;        // NGRP1 * C1

    int gs = blockIdx.x;
    int b = gs / S, s = gs - b * S;
    int tid = threadIdx.x;

    int* sidx = (int*)pmax;
    for (int e = tid; e < NS; e += T)
        sidx[e] = idx[(size_t)gs * NS + e];
    __syncthreads();

    {
        float cx = newxyz[gs * 3 + 0], cy = newxyz[gs * 3 + 1], cz = newxyz[gs * 3 + 2];
        for (int e = tid; e < NS; e += T) {
            const float* p = xyz + ((size_t)b * N + sidx[e]) * 3;
            xs[0 * LD + e] = p[0] - cx;
            xs[1 * LD + e] = p[1] - cy;
            xs[2 * LD + e] = p[2] - cz;
        }
    }
    __syncthreads();

    // ---- layer 0: acc = Y[sample] ; += W_xyz @ rel_xyz ; relu -> mid ----
    {
        int cq = tid % CQ0;
        int n8 = tid / CQ0;
        const float* Yb = Y + (size_t)b * N * C0 + 4 * cq;
        u64 acc[4][NO0 / 2];
#pragma unroll
        for (int j = 0; j < NO0 / 2; j++) {
            float4 y0 = *reinterpret_cast<const float4*>(Yb + (size_t)sidx[n8 * NO0 + 2 * j + 0] * C0);
            float4 y1 = *reinterpret_cast<const float4*>(Yb + (size_t)sidx[n8 * NO0 + 2 * j + 1] * C0);
            acc[0][j] = packpair(y0.x, y1.x);
            acc[1][j] = packpair(y0.y, y1.y);
            acc[2][j] = packpair(y0.z, y1.z);
            acc[3][j] = packpair(y0.w, y1.w);
        }
        const float* xrow = xs + n8 * NO0;
        const float* wptr = w0x + 4 * cq;
#pragma unroll
        for (int k = 0; k < 3; k++) {
            float4 w = *reinterpret_cast<const float4*>(wptr + k * C0);
            ulonglong2 v[NO0 / 4];
            const ulonglong2* xr = reinterpret_cast<const ulonglong2*>(xrow + k * LD);
#pragma unroll
            for (int j = 0; j < NO0 / 4; j++) v[j] = xr[j];
            float wk[4] = {w.x, w.y, w.z, w.w};
#pragma unroll
            for (int i = 0; i < 4; i++) {
                u64 w2 = pack2(wk[i]);
#pragma unroll
                for (int j = 0; j < NO0 / 4; j++) {
                    acc[i][2 * j + 0] = ffma2(w2, v[j].x, acc[i][2 * j + 0]);
                    acc[i][2 * j + 1] = ffma2(w2, v[j].y, acc[i][2 * j + 1]);
                }
            }
        }
#pragma unroll
        for (int i = 0; i < 4; i++) {
            float* mrow = mid + (4 * cq + i) * LD + n8 * NO0;
#pragma unroll
            for (int j = 0; j < NO0 / 2; j++) {
                float lo, hi;
                unpack2(acc[i][j], lo, hi);
                float2 r;
                r.x = fmaxf(lo, 0.0f);
                r.y = fmaxf(hi, 0.0f);
                *reinterpret_cast<float2*>(mrow + 2 * j) = r;
            }
        }
    }
    __syncthreads();

    // ---- layer 1 + partial max ----
    {
        int cq = tid % CQ1;
        int n8 = tid / CQ1;
        u64 acc[4][NO1 / 2];
        {
            float4 bv = *reinterpret_cast<const float4*>(b1 + 4 * cq);
            float bk[4] = {bv.x, bv.y, bv.z, bv.w};
#pragma unroll
            for (int i = 0; i < 4; i++) {
                u64 p = pack2(bk[i]);
#pragma unroll
                for (int j = 0; j < NO1 / 2; j++) acc[i][j] = p;
            }
        }
        const float* mrowb = mid + n8 * NO1;
        const float* wptr = w1T + 4 * cq;
#pragma unroll 4
        for (int k = 0; k < C0; k++) {
            float4 w = *reinterpret_cast<const float4*>(wptr + k * C1);
            ulonglong2 v[NO1 / 4];
            const ulonglong2* mr = reinterpret_cast<const ulonglong2*>(mrowb + k * LD);
#pragma unroll
            for (int j = 0; j < NO1 / 4; j++) v[j] = mr[j];
            float wk[4] = {w.x, w.y, w.z, w.w};
#pragma unroll
            for (int i = 0; i < 4; i++) {
                u64 w2 = pack2(wk[i]);
#pragma unroll
                for (int j = 0; j < NO1 / 4; j++) {
                    acc[i][2 * j + 0] = ffma2(w2, v[j].x, acc[i][2 * j + 0]);
                    acc[i][2 * j + 1] = ffma2(w2, v[j].y, acc[i][2 * j + 1]);
                }
            }
        }
#pragma unroll
        for (int i = 0; i < 4; i++) {
            float m = -3.4e38f;
#pragma unroll
            for (int j = 0; j < NO1 / 2; j++) {
                float lo, hi;
                unpack2(acc[i][j], lo, hi);
                m = fmaxf(m, fmaxf(lo, hi));
            }
            pmax[n8 * C1 + 4 * cq + i] = m;
        }
    }
    __syncthreads();

    // ---- final max + relu + store ----
    for (int ch = tid; ch < C1; ch += T) {
        float m = pmax[ch];
#pragma unroll
        for (int j = 1; j < NGRP1; j++) m = fmaxf(m, pmax[j * C1 + ch]);
        m = fmaxf(m, 0.0f);
        if (FINAL)
            out[(size_t)b * C1 * S + (size_t)ch * S + s] = m;   // (B, C, S)
        else
            out[(size_t)gs * C1 + ch] = m;                      // (B, S, C)
    }
}

// ---------------------------------------------------------------------------
extern "C" void kernel_launch(void* const* d_in, const int* in_sizes, int n_in,
                              void* d_out, int out_size)
{
    (void)in_sizes; (void)n_in; (void)out_size;
    const float* pc = (const float*)d_in[0];

    float *nx1, *nx2, *nx3, *f1, *f2, *y1, *y2;
    int* idxb;
    float *w0T, *w1T, *w2x, *w2f, *w3T, *w4x, *w4f, *w5T;
    float *b0, *b1, *b2, *b3, *b4, *b5;
    cudaGetSymbolAddress((void**)&nx1, g_nx1);
    cudaGetSymbolAddress((void**)&nx2, g_nx2);
    cudaGetSymbolAddress((void**)&nx3, g_nx3);
    cudaGetSymbolAddress((void**)&idxb, g_idxbuf);
    cudaGetSymbolAddress((void**)&f1, g_f1);
    cudaGetSymbolAddress((void**)&f2, g_f2);
    cudaGetSymbolAddress((void**)&y1, g_y1);
    cudaGetSymbolAddress((void**)&y2, g_y2);
    cudaGetSymbolAddress((void**)&w0T, g_w0T); cudaGetSymbolAddress((void**)&b0, g_b0);
    cudaGetSymbolAddress((void**)&w1T, g_w1T); cudaGetSymbolAddress((void**)&b1, g_b1);
    cudaGetSymbolAddress((void**)&w2x, g_w2x); cudaGetSymbolAddress((void**)&w2f, g_w2f);
    cudaGetSymbolAddress((void**)&b2, g_b2);
    cudaGetSymbolAddress((void**)&w3T, g_w3T); cudaGetSymbolAddress((void**)&b3, g_b3);
    cudaGetSymbolAddress((void**)&w4x, g_w4x); cudaGetSymbolAddress((void**)&w4f, g_w4f);
    cudaGetSymbolAddress((void**)&b4, g_b4);
    cudaGetSymbolAddress((void**)&w5T, g_w5T); cudaGetSymbolAddress((void**)&b5, g_b5);

    FoldArgs fa;
    const int cins[6]  = {9, 32, 67, 128, 131, 256};
    const int couts[6] = {32, 64, 128, 128, 256, 256};
    float* wTs[6] = {w0T, w1T, w2x, w3T, w4x, w5T};
    float* wFs[6] = {nullptr, nullptr, w2f, nullptr, w4f, nullptr};
    float* bss[6] = {b0, b1, b2, b3, b4, b5};
    for (int l = 0; l < 6; l++) {
        fa.w[l]  = (const float*)d_in[1 + 5 * l];
        fa.g[l]  = (const float*)d_in[2 + 5 * l];
        fa.be[l] = (const float*)d_in[3 + 5 * l];
        fa.rm[l] = (const float*)d_in[4 + 5 * l];
        fa.rv[l] = (const float*)d_in[5 + 5 * l];
        fa.wT[l] = wTs[l]; fa.wF[l] = wFs[l]; fa.bias[l] = bss[l];
        fa.cin[l] = cins[l]; fa.cout[l] = couts[l];
    }
    fold_all_kernel<<<dim3(72, 6), 256>>>(fa);

    const float rr0 = (float)(0.02 * 0.02);
    const float rr1 = (float)(0.04 * 0.04);
    const float rr2 = (float)(0.08 * 0.08);

    // dynamic smem (bytes)
    const int smem0 = ((6 + 32) * 132 + 512) * 4;           // 22112
    const int smem1 = ((3 + 128) * 36 + 512) * 4;           // 20912
    const int smem2 = ((3 + 256) * 20 + 512) * 4;           // 22768

    auto k0 = sa_mlp0_kernel<6, 32, 64, 32, 4, 128, 8, 16>;
    auto k1 = sa12_kernel<128, 128, 32, 128, 8, 8, false>;
    auto k2 = sa12_kernel<256, 256, 16, 128, 8, 8, true>;

    // ---- stage 0: N=4096 -> S=128 ----
    fps_kernel<4096, 128, 256><<<B, 256>>>(pc, nx1);
    ballquery_kernel<32><<<(B * S0) / 4, 128>>>(nx1, pc, idxb, N0, S0, rr0);
    k0<<<(B * S0) / 4, 128, smem0>>>(pc, nx1, idxb, w0T, b0, w1T, b1, f1, N0, S0);

    // ---- stage 1: N=128 -> S=64 ----
    precompute_kernel<64, 128><<<B * S0, 128>>>(f1, w2f, b2, y1);
    fps_kernel<128, 64, 128><<<B, 128>>>(nx1, nx2);
    ballquery_kernel<32><<<(B * S1) / 4, 128>>>(nx2, nx1, idxb, S0, S1, rr1);
    k1<<<B * S1, 128, smem1>>>(nx1, y1, nx2, idxb, w2x, w3T, b3, f2, S0, S1);

    // ---- stage 2: N=64 -> S=32 ----
    precompute_kernel<128, 256><<<B * S1, 256>>>(f2, w4f, b4, y2);
    fps_kernel<64, 32, 64><<<B, 64>>>(nx2, nx3);
    ballquery_kernel<16><<<(B * S2) / 4, 128>>>(nx3, nx2, idxb, S1, S2, rr2);
    k2<<<B * S2, 128, smem2>>>(nx2, y2, nx3, idxb, w4x, w5T, b5, (float*)d_out, S1, S2);
}

// round 13
// speedup vs baseline: 1.1750x; 1.1750x over previous
#include <cuda_runtime.h>
#include <cstdint>

// ---------------------------------------------------------------------------
// PointNet++ (3 SA stages), B=64, N=4096, fp32.
// Round 12: stage1/2 as batched tensor-core GEMMs (m16n8k8.tf32, 3xTF32
// split precision, fragments validated in R8). One block = 128 samples,
// weights pre-split to tf32 hi/lo at fold time, sample-major smem.
// Stage0 stays SIMT/FFMA2 (proven 32us).
// ---------------------------------------------------------------------------

static constexpr int B   = 64;
static constexpr int N0  = 4096;
static constexpr int S0  = 128, NSAMP0 = 32;
static constexpr int S1  = 64;
static constexpr int S2  = 32;

// ------------------------- device scratch (no allocs) ----------------------
__device__ float g_nx1[B * S0 * 3];
__device__ float g_nx2[B * S1 * 3];
__device__ float g_nx3[B * S2 * 3];
__device__ int   g_idxbuf[B * S0 * NSAMP0];
__device__ __align__(16) float g_f1[B * S0 * 64];     // stage0 out, (B,S0,64)
__device__ __align__(16) float g_f2[B * S1 * 128];    // stage1 out, (B,S1,128)

// stage0 (SIMT): k-major folded weights, CIN folded 9->6
__device__ __align__(16) float g_w0T[6 * 32];     __device__ __align__(16) float g_b0[32];
__device__ __align__(16) float g_w1T[32 * 64];    __device__ __align__(16) float g_b1[64];
// stage1/2 (mma): row-major o x KP, tf32 hi/lo pre-split, cols = [feat|xyz|pad]
__device__ __align__(16) float g_w2hi[128 * 72];  __device__ __align__(16) float g_w2lo[128 * 72];
__device__ __align__(16) float g_b2[128];
__device__ __align__(16) float g_w3hi[128 * 128]; __device__ __align__(16) float g_w3lo[128 * 128];
__device__ __align__(16) float g_b3[128];
__device__ __align__(16) float g_w4hi[256 * 136]; __device__ __align__(16) float g_w4lo[256 * 136];
__device__ __align__(16) float g_b4[256];
__device__ __align__(16) float g_w5hi[256 * 256]; __device__ __align__(16) float g_w5lo[256 * 256];
__device__ __align__(16) float g_b5[256];

// ------------------------- f32x2 helpers (stage0 SIMT) ---------------------
typedef unsigned long long u64;

__device__ __forceinline__ u64 pack2(float x) {
    u64 r;
    asm("mov.b64 %0, {%1, %2};" : "=l"(r) : "f"(x), "f"(x));
    return r;
}
__device__ __forceinline__ void unpack2(u64 v, float& lo, float& hi) {
    asm("mov.b64 {%0, %1}, %2;" : "=f"(lo), "=f"(hi) : "l"(v));
}
__device__ __forceinline__ u64 ffma2(u64 a, u64 b, u64 c) {
    u64 d;
    asm("fma.rn.f32x2 %0, %1, %2, %3;" : "=l"(d) : "l"(a), "l"(b), "l"(c));
    return d;
}

// ------------------------- tf32 helpers ------------------------------------
__device__ __forceinline__ void split_tf32(float x, uint32_t& hi, uint32_t& lo) {
    asm("cvt.rna.tf32.f32 %0, %1;" : "=r"(hi) : "f"(x));
    float hif = __uint_as_float(hi);
    float lof = __fsub_rn(x, hif);
    asm("cvt.rna.tf32.f32 %0, %1;" : "=r"(lo) : "f"(lof));
}
__device__ __forceinline__ void mma_tf32(float* c, const uint32_t* a, const uint32_t* b) {
    asm("mma.sync.aligned.m16n8k8.row.col.f32.tf32.tf32.f32 "
        "{%0,%1,%2,%3}, {%4,%5,%6,%7}, {%8,%9}, {%0,%1,%2,%3};"
        : "+f"(c[0]), "+f"(c[1]), "+f"(c[2]), "+f"(c[3])
        : "r"(a[0]), "r"(a[1]), "r"(a[2]), "r"(a[3]), "r"(b[0]), "r"(b[1]));
}

// ------------------------- merged BN fold ----------------------------------
struct FoldArgs {
    const float* w[6]; const float* g[6]; const float* be[6];
    const float* rm[6]; const float* rv[6];
    float* wT[6];      // fp32 k-major (l0,l1) or tf32 hi (l2..5)
    float* wLo[6];     // tf32 lo (l2..5)
    float* bias[6];
    int cin[6]; int kp[6]; int cout[6];
};

__global__ void fold_all_kernel(FoldArgs a)
{
    int l = blockIdx.y;
    int cin = a.cin[l], KP = a.kp[l], cout = a.cout[l];
    const float* w = a.w[l]; const float* g = a.g[l]; const float* be = a.be[l];
    const float* rm = a.rm[l]; const float* rv = a.rv[l];
    float* wT = a.wT[l]; float* wLo = a.wLo[l]; float* bias = a.bias[l];
    int i = blockIdx.x * blockDim.x + threadIdx.x;
    if (i < cout) {
        float s = g[i] * rsqrtf(rv[i] + 1e-5f);
        bias[i] = be[i] - s * rm[i];
    }
    if (l == 0) {
        // k-major, fold 9 -> 6 rows (dup abs-xyz)
        int tot = cout * 6;
        for (int e = i; e < tot; e += gridDim.x * blockDim.x) {
            int o = e / 6, k = e - o * 6;
            float s = g[o] * rsqrtf(rv[o] + 1e-5f);
            float val = (k < 3) ? w[o * 9 + k] : (w[o * 9 + k] + w[o * 9 + k + 3]);
            wT[k * cout + o] = val * s;
        }
    } else if (l == 1) {
        int tot = cout * cin;
        for (int e = i; e < tot; e += gridDim.x * blockDim.x) {
            int o = e / cin, k = e - o * cin;
            float s = g[o] * rsqrtf(rv[o] + 1e-5f);
            wT[k * cout + o] = w[e] * s;
        }
    } else {
        // mma weights: row-major o x KP, tf32 hi/lo. For l=2,4 reorder cols
        // to [feat(CF) | xyz(3) | pad]; l=3,5 plain (cin == KP).
        bool reord = (l == 2 || l == 4);
        int CF = cin - 3;
        int tot = cout * KP;
        for (int e = i; e < tot; e += gridDim.x * blockDim.x) {
            int o = e / KP, k = e - o * KP;
            float s = g[o] * rsqrtf(rv[o] + 1e-5f);
            float val = 0.0f;
            if (reord) {
                int ko = (k < CF) ? (3 + k) : ((k < CF + 3) ? (k - CF) : -1);
                if (ko >= 0) val = w[o * cin + ko] * s;
            } else {
                if (k < cin) val = w[o * cin + k] * s;
            }
            uint32_t hi, lo;
            split_tf32(val, hi, lo);
            wT[e]  = __uint_as_float(hi);
            wLo[e] = __uint_as_float(lo);
        }
    }
}

// ------------------------- farthest point sampling -------------------------
template<int N, int NPOINT, int T>
__global__ void __launch_bounds__(T) fps_kernel(const float* __restrict__ xyz,
                                                float* __restrict__ newxyz)
{
    constexpr int PPT = N / T;
    int b = blockIdx.x;
    int tid = threadIdx.x;
    const float* x = xyz + (size_t)b * N * 3;

    float px[PPT], py[PPT], pz[PPT], dist[PPT];
#pragma unroll
    for (int i = 0; i < PPT; i++) {
        int p = tid + i * T;
        px[i] = x[p * 3 + 0];
        py[i] = x[p * 3 + 1];
        pz[i] = x[p * 3 + 2];
        dist[i] = 1e10f;
    }

    __shared__ float cur[3];
    __shared__ float wv[T / 32];
    __shared__ int   wi[T / 32];

    if (tid == 0) {
        cur[0] = x[0]; cur[1] = x[1]; cur[2] = x[2];
        float* o = newxyz + (size_t)b * NPOINT * 3;
        o[0] = x[0]; o[1] = x[1]; o[2] = x[2];
    }
    __syncthreads();

    for (int j = 1; j < NPOINT; j++) {
        float cx = cur[0], cy = cur[1], cz = cur[2];
        float bv = -1.0f;
        int   bi = 0x7fffffff;
#pragma unroll
        for (int i = 0; i < PPT; i++) {
            float dx = px[i] - cx, dy = py[i] - cy, dz = pz[i] - cz;
            float d = __fadd_rn(__fadd_rn(__fmul_rn(dx, dx), __fmul_rn(dy, dy)),
                                __fmul_rn(dz, dz));
            float nd = fminf(dist[i], d);
            dist[i] = nd;
            int gidx = tid + i * T;
            if (nd > bv || (nd == bv && gidx < bi)) { bv = nd; bi = gidx; }
        }
#pragma unroll
        for (int off = 16; off > 0; off >>= 1) {
            float ov = __shfl_down_sync(0xffffffffu, bv, off);
            int   oi = __shfl_down_sync(0xffffffffu, bi, off);
            if (ov > bv || (ov == bv && oi < bi)) { bv = ov; bi = oi; }
        }
        if ((tid & 31) == 0) { wv[tid >> 5] = bv; wi[tid >> 5] = bi; }
        __syncthreads();
        if (tid < 32) {
            constexpr int NW = T / 32;
            bv = (tid < NW) ? wv[tid] : -2.0f;
            bi = (tid < NW) ? wi[tid] : 0x7fffffff;
#pragma unroll
            for (int off = 16; off > 0; off >>= 1) {
                float ov = __shfl_down_sync(0xffffffffu, bv, off);
                int   oi = __shfl_down_sync(0xffffffffu, bi, off);
                if (ov > bv || (ov == bv && oi < bi)) { bv = ov; bi = oi; }
            }
            if (tid == 0) {
                const float* p = x + (size_t)bi * 3;
                float nx = p[0], ny = p[1], nz = p[2];
                cur[0] = nx; cur[1] = ny; cur[2] = nz;
                float* o = newxyz + ((size_t)b * NPOINT + j) * 3;
                o[0] = nx; o[1] = ny; o[2] = nz;
            }
        }
        __syncthreads();
    }
}

// ------------------------- ball query --------------------------------------
template<int NS>
__global__ void ballquery_kernel(const float* __restrict__ newxyz,
                                 const float* __restrict__ xyz,
                                 int* __restrict__ idxout,
                                 int N, int S, float rr)
{
    __shared__ int rows[4][NS];
    int lane = threadIdx.x & 31;
    int wip  = threadIdx.x >> 5;
    int q = blockIdx.x * 4 + wip;
    int b = q / S;
    const float* nq = newxyz + (size_t)q * 3;
    float qx = nq[0], qy = nq[1], qz = nq[2];
    const float* x = xyz + (size_t)b * N * 3;
    int* row = rows[wip];
    int cnt = 0;

    for (int base = 0; base < N; base += 32) {
        if (cnt >= NS) break;
        int p = base + lane;
        float dx = x[p * 3 + 0] - qx;
        float dy = x[p * 3 + 1] - qy;
        float dz = x[p * 3 + 2] - qz;
        float d = __fadd_rn(__fadd_rn(__fmul_rn(dx, dx), __fmul_rn(dy, dy)),
                            __fmul_rn(dz, dz));
        bool hit = d < rr;
        unsigned m = __ballot_sync(0xffffffffu, hit);
        if (hit) {
            int pos = cnt + __popc(m & ((1u << lane) - 1u));
            if (pos < NS) row[pos] = p;
        }
        cnt += __popc(m);
    }
    __syncwarp();
    int first = (cnt > 0) ? row[0] : 0;
    for (int t = cnt + lane; t < NS; t += 32) row[t] = first;
    __syncwarp();
    for (int t = lane; t < NS; t += 32) idxout[(size_t)q * NS + t] = row[t];
}

// ------------------------- stage0 SIMT MLP (proven R5 config) ---------------
template<int CIN, int C0, int C1, int NS, int G, int T, int NO0, int NO1>
__global__ void __launch_bounds__(T) sa_mlp0_kernel(
    const float* __restrict__ xyz,
    const float* __restrict__ newxyz, const int* __restrict__ idx,
    const float* __restrict__ w0T, const float* __restrict__ b0,
    const float* __restrict__ w1T, const float* __restrict__ b1,
    float* __restrict__ out, int N, int S)
{
    constexpr int SB = NS * G;
    constexpr int LD = SB + 4;
    constexpr int CQ0 = C0 / 4, NGRP0 = SB / NO0;
    constexpr int CQ1 = C1 / 4, NGRP1 = SB / NO1;
    static_assert(CQ0 * NGRP0 == T, "layer0 mapping");
    static_assert(CQ1 * NGRP1 == T, "layer1 mapping");
    constexpr int OPG = NS / NO1;

    extern __shared__ __align__(16) float smem[];
    float* xs   = smem;
    float* mid  = xs + CIN * LD;
    float* pmax = mid + C0 * LD;

    int gs0 = blockIdx.x * G;
    int b = gs0 / S;
    int tid = threadIdx.x;

    int* sidx = (int*)pmax;
    for (int e = tid; e < SB; e += T)
        sidx[e] = idx[(size_t)(gs0 + e / NS) * NS + (e % NS)];
    __syncthreads();

    for (int e = tid; e < SB; e += T) {
        int g = e / NS;
        int id = sidx[e];
        const float* p = xyz + ((size_t)b * N + id) * 3;
        const float* c = newxyz + (size_t)(gs0 + g) * 3;
        float ax = p[0], ay = p[1], az = p[2];
        xs[0 * LD + e] = ax - c[0];
        xs[1 * LD + e] = ay - c[1];
        xs[2 * LD + e] = az - c[2];
        xs[3 * LD + e] = ax; xs[4 * LD + e] = ay; xs[5 * LD + e] = az;
    }
    __syncthreads();

    {
        int cq = tid % CQ0;
        int n8 = tid / CQ0;
        u64 acc[4][NO0 / 2];
        {
            float4 bv = *reinterpret_cast<const float4*>(b0 + 4 * cq);
            float bk[4] = {bv.x, bv.y, bv.z, bv.w};
#pragma unroll
            for (int i = 0; i < 4; i++) {
                u64 p = pack2(bk[i]);
#pragma unroll
                for (int j = 0; j < NO0 / 2; j++) acc[i][j] = p;
            }
        }
        const float* xrow = xs + n8 * NO0;
        const float* wptr = w0T + 4 * cq;
#pragma unroll 4
        for (int k = 0; k < CIN; k++) {
            float4 w = *reinterpret_cast<const float4*>(wptr + k * C0);
            ulonglong2 v[NO0 / 4];
            const ulonglong2* xr = reinterpret_cast<const ulonglong2*>(xrow + k * LD);
#pragma unroll
            for (int j = 0; j < NO0 / 4; j++) v[j] = xr[j];
            float wk[4] = {w.x, w.y, w.z, w.w};
#pragma unroll
            for (int i = 0; i < 4; i++) {
                u64 w2 = pack2(wk[i]);
#pragma unroll
                for (int j = 0; j < NO0 / 4; j++) {
                    acc[i][2 * j + 0] = ffma2(w2, v[j].x, acc[i][2 * j + 0]);
                    acc[i][2 * j + 1] = ffma2(w2, v[j].y, acc[i][2 * j + 1]);
                }
            }
        }
#pragma unroll
        for (int i = 0; i < 4; i++) {
            float* mrow = mid + (4 * cq + i) * LD + n8 * NO0;
#pragma unroll
            for (int j = 0; j < NO0 / 2; j++) {
                float lo, hi;
                unpack2(acc[i][j], lo, hi);
                float2 r;
                r.x = fmaxf(lo, 0.0f);
                r.y = fmaxf(hi, 0.0f);
                *reinterpret_cast<float2*>(mrow + 2 * j) = r;
            }
        }
    }
    __syncthreads();

    {
        int cq = tid % CQ1;
        int n8 = tid / CQ1;
        u64 acc[4][NO1 / 2];
        {
            float4 bv = *reinterpret_cast<const float4*>(b1 + 4 * cq);
            float bk[4] = {bv.x, bv.y, bv.z, bv.w};
#pragma unroll
            for (int i = 0; i < 4; i++) {
                u64 p = pack2(bk[i]);
#pragma unroll
                for (int j = 0; j < NO1 / 2; j++) acc[i][j] = p;
            }
        }
        const float* mrowb = mid + n8 * NO1;
        const float* wptr = w1T + 4 * cq;
#pragma unroll 4
        for (int k = 0; k < C0; k++) {
            float4 w = *reinterpret_cast<const float4*>(wptr + k * C1);
            ulonglong2 v[NO1 / 4];
            const ulonglong2* mr = reinterpret_cast<const ulonglong2*>(mrowb + k * LD);
#pragma unroll
            for (int j = 0; j < NO1 / 4; j++) v[j] = mr[j];
            float wk[4] = {w.x, w.y, w.z, w.w};
#pragma unroll
            for (int i = 0; i < 4; i++) {
                u64 w2 = pack2(wk[i]);
#pragma unroll
                for (int j = 0; j < NO1 / 4; j++) {
                    acc[i][2 * j + 0] = ffma2(w2, v[j].x, acc[i][2 * j + 0]);
                    acc[i][2 * j + 1] = ffma2(w2, v[j].y, acc[i][2 * j + 1]);
                }
            }
        }
#pragma unroll
        for (int i = 0; i < 4; i++) {
            float m = -3.4e38f;
#pragma unroll
            for (int j = 0; j < NO1 / 2; j++) {
                float lo, hi;
                unpack2(acc[i][j], lo, hi);
                m = fmaxf(m, fmaxf(lo, hi));
            }
            pmax[n8 * C1 + 4 * cq + i] = m;
        }
    }
    __syncthreads();

    for (int e = tid; e < G * C1; e += T) {
        int g = e / C1, ch = e - g * C1;
        float m = pmax[(g * OPG) * C1 + ch];
#pragma unroll
        for (int j = 1; j < OPG; j++)
            m = fmaxf(m, pmax[(g * OPG + j) * C1 + ch]);
        m = fmaxf(m, 0.0f);
        int gs = gs0 + g;
        out[(size_t)gs * C1 + ch] = m;                      // (B, S, C)
    }
}

// ------------------------- stage1/2 batched mma GEMM ------------------------
// One block = 128 samples (NG groups), 256 threads = 8 warps.
// Sample-major smem: xs[sample][k] pitch KP, mid[sample][c] pitch MP
// (both pitches = 4 mod 8 -> conflict-free B-fragment LDS).
// Weight cols = [feat(CF) | xyz(3) | pad], pre-split tf32 hi/lo in global.
// 3xTF32: acc += ahi*blo + alo*bhi + ahi*bhi.
template<int C0, int C1, int CF, int K0P, int NS, int KP, int MP, bool FINAL>
__global__ void __launch_bounds__(256) sa_gemm_kernel(
    const float* __restrict__ xyz, const float* __restrict__ feats,
    const float* __restrict__ newxyz, const int* __restrict__ idx,
    const float* __restrict__ w0hi, const float* __restrict__ w0lo,
    const float* __restrict__ b0v,
    const float* __restrict__ w1hi, const float* __restrict__ w1lo,
    const float* __restrict__ b1v,
    float* __restrict__ out, int N, int S)
{
    constexpr int K0  = CF + 3;
    constexpr int NG  = 128 / NS;      // groups per block
    constexpr int NSG = NS / 8;        // n8 tiles per group
    constexpr int MT0 = C0 / 128;      // m16 tiles per warp
    constexpr int MT1 = C1 / 128;
    constexpr int K0S = K0P / 8;
    constexpr int K1S = C0 / 8;
    constexpr int CF4 = CF / 4;

    extern __shared__ __align__(16) float smem[];
    float* xs  = smem;                  // 128 * KP
    float* mid = xs + 128 * KP;         // 128 * MP
    int*  sidx = (int*)(mid + 128 * MP);

    int NT = S / NG;                    // n-tiles (blocks) per batch
    int bt = blockIdx.x;
    int b  = bt / NT, nt = bt - b * NT;
    int gs0 = b * S + nt * NG;

    int tid  = threadIdx.x;
    int lane = tid & 31, warp = tid >> 5;
    int gid  = lane >> 2, tl = lane & 3;

    // ---- gather ----
    for (int e = tid; e < 128; e += 256)
        sidx[e] = idx[(size_t)(gs0 + e / NS) * NS + (e % NS)];
    __syncthreads();

    // feats (float4, coalesced per sample row)
    for (int e = tid; e < 128 * CF4; e += 256) {
        int n = e / CF4, c4 = e - n * CF4;
        float4 v = reinterpret_cast<const float4*>(feats)[((size_t)b * N + sidx[n]) * CF4 + c4];
        *reinterpret_cast<float4*>(xs + n * KP + 4 * c4) = v;
    }
    // rel xyz at cols CF..CF+2
    for (int e = tid; e < 128; e += 256) {
        const float* p = xyz + ((size_t)b * N + sidx[e]) * 3;
        const float* c = newxyz + (size_t)(gs0 + e / NS) * 3;
        xs[e * KP + CF + 0] = p[0] - c[0];
        xs[e * KP + CF + 1] = p[1] - c[1];
        xs[e * KP + CF + 2] = p[2] - c[2];
    }
    // zero pad cols K0..K0P-1
    for (int e = tid; e < (K0P - K0) * 128; e += 256) {
        int r = e / 128, n = e - r * 128;
        xs[n * KP + K0 + r] = 0.0f;
    }
    __syncthreads();

    const uint32_t* w0h = reinterpret_cast<const uint32_t*>(w0hi);
    const uint32_t* w0l = reinterpret_cast<const uint32_t*>(w0lo);
    const uint32_t* w1h = reinterpret_cast<const uint32_t*>(w1hi);
    const uint32_t* w1l = reinterpret_cast<const uint32_t*>(w1lo);

    // ---- layer 0: mid = relu(W0 @ X + b0), chunks of 8 n8-tiles ----
#pragma unroll 1
    for (int ch = 0; ch < 2; ch++) {
        float acc[MT0][8][4];
#pragma unroll
        for (int mt = 0; mt < MT0; mt++) {
            int r0 = warp * MT0 * 16 + mt * 16 + gid;
            float bb0 = b0v[r0], bb1 = b0v[r0 + 8];
#pragma unroll
            for (int t = 0; t < 8; t++) {
                acc[mt][t][0] = bb0; acc[mt][t][1] = bb0;
                acc[mt][t][2] = bb1; acc[mt][t][3] = bb1;
            }
        }
#pragma unroll 1
        for (int ks = 0; ks < K0S; ks++) {
            uint32_t ah[MT0][4], al[MT0][4];
#pragma unroll
            for (int mt = 0; mt < MT0; mt++) {
                int r0 = warp * MT0 * 16 + mt * 16 + gid;
                const uint32_t* ph = w0h + (size_t)r0 * K0P + ks * 8 + tl;
                ah[mt][0] = ph[0]; ah[mt][1] = ph[8 * K0P];
                ah[mt][2] = ph[4]; ah[mt][3] = ph[8 * K0P + 4];
                const uint32_t* pl = w0l + (size_t)r0 * K0P + ks * 8 + tl;
                al[mt][0] = pl[0]; al[mt][1] = pl[8 * K0P];
                al[mt][2] = pl[4]; al[mt][3] = pl[8 * K0P + 4];
            }
#pragma unroll
            for (int t = 0; t < 8; t++) {
                int col = ch * 64 + t * 8 + gid;
                const float* xp = xs + col * KP + ks * 8 + tl;
                float x0 = xp[0], x1 = xp[4];
                uint32_t bh[2], bl[2];
                split_tf32(x0, bh[0], bl[0]);
                split_tf32(x1, bh[1], bl[1]);
#pragma unroll
                for (int mt = 0; mt < MT0; mt++) {
                    mma_tf32(acc[mt][t], ah[mt], bl);
                    mma_tf32(acc[mt][t], al[mt], bh);
                    mma_tf32(acc[mt][t], ah[mt], bh);
                }
            }
        }
        // store mid with relu (sample-major)
#pragma unroll
        for (int mt = 0; mt < MT0; mt++) {
            int r0 = warp * MT0 * 16 + mt * 16 + gid;
#pragma unroll
            for (int t = 0; t < 8; t++) {
                int colb = ch * 64 + t * 8 + 2 * tl;
                mid[(colb + 0) * MP + r0]     = fmaxf(acc[mt][t][0], 0.0f);
                mid[(colb + 1) * MP + r0]     = fmaxf(acc[mt][t][1], 0.0f);
                mid[(colb + 0) * MP + r0 + 8] = fmaxf(acc[mt][t][2], 0.0f);
                mid[(colb + 1) * MP + r0 + 8] = fmaxf(acc[mt][t][3], 0.0f);
            }
        }
    }
    __syncthreads();

    // ---- layer 1 + maxpool ----
#pragma unroll 1
    for (int ch = 0; ch < 2; ch++) {
        float acc[MT1][8][4];
#pragma unroll
        for (int mt = 0; mt < MT1; mt++) {
            int r0 = warp * MT1 * 16 + mt * 16 + gid;
            float bb0 = b1v[r0], bb1 = b1v[r0 + 8];
#pragma unroll
            for (int t = 0; t < 8; t++) {
                acc[mt][t][0] = bb0; acc[mt][t][1] = bb0;
                acc[mt][t][2] = bb1; acc[mt][t][3] = bb1;
            }
        }
#pragma unroll 1
        for (int ks = 0; ks < K1S; ks++) {
            uint32_t ah[MT1][4], al[MT1][4];
#pragma unroll
            for (int mt = 0; mt < MT1; mt++) {
                int r0 = warp * MT1 * 16 + mt * 16 + gid;
                const uint32_t* ph = w1h + (size_t)r0 * C0 + ks * 8 + tl;
                ah[mt][0] = ph[0]; ah[mt][1] = ph[8 * C0];
                ah[mt][2] = ph[4]; ah[mt][3] = ph[8 * C0 + 4];
                const uint32_t* pl = w1l + (size_t)r0 * C0 + ks * 8 + tl;
                al[mt][0] = pl[0]; al[mt][1] = pl[8 * C0];
                al[mt][2] = pl[4]; al[mt][3] = pl[8 * C0 + 4];
            }
#pragma unroll
            for (int t = 0; t < 8; t++) {
                int col = ch * 64 + t * 8 + gid;
                const float* xp = mid + col * MP + ks * 8 + tl;
                float x0 = xp[0], x1 = xp[4];
                uint32_t bh[2], bl[2];
                split_tf32(x0, bh[0], bl[0]);
                split_tf32(x1, bh[1], bl[1]);
#pragma unroll
                for (int mt = 0; mt < MT1; mt++) {
                    mma_tf32(acc[mt][t], ah[mt], bl);
                    mma_tf32(acc[mt][t], al[mt], bh);
                    mma_tf32(acc[mt][t], ah[mt], bh);
                }
            }
        }
        // maxpool per group (chunk holds 8/NSG groups) + relu + store
        constexpr int GPC = 8 / NSG;
#pragma unroll
        for (int mt = 0; mt < MT1; mt++) {
            int r0 = warp * MT1 * 16 + mt * 16 + gid;
#pragma unroll
            for (int gl = 0; gl < GPC; gl++) {
                float m0 = -3.4e38f, m1 = -3.4e38f;
#pragma unroll
                for (int tt = 0; tt < NSG; tt++) {
                    int t = gl * NSG + tt;
                    m0 = fmaxf(m0, fmaxf(acc[mt][t][0], acc[mt][t][1]));
                    m1 = fmaxf(m1, fmaxf(acc[mt][t][2], acc[mt][t][3]));
                }
                m0 = fmaxf(m0, __shfl_xor_sync(0xffffffffu, m0, 1));
                m0 = fmaxf(m0, __shfl_xor_sync(0xffffffffu, m0, 2));
                m1 = fmaxf(m1, __shfl_xor_sync(0xffffffffu, m1, 1));
                m1 = fmaxf(m1, __shfl_xor_sync(0xffffffffu, m1, 2));
                if (tl == 0) {
                    int g  = ch * GPC + gl;
                    int gs = gs0 + g;
                    int s  = gs - b * S;
                    float v0 = fmaxf(m0, 0.0f);
                    float v1 = fmaxf(m1, 0.0f);
                    if (FINAL) {
                        out[(size_t)b * C1 * S + (size_t)r0 * S + s]       = v0;
                        out[(size_t)b * C1 * S + (size_t)(r0 + 8) * S + s] = v1;
                    } else {
                        out[(size_t)gs * C1 + r0]     = v0;
                        out[(size_t)gs * C1 + r0 + 8] = v1;
                    }
                }
            }
        }
    }
}

// ---------------------------------------------------------------------------
extern "C" void kernel_launch(void* const* d_in, const int* in_sizes, int n_in,
                              void* d_out, int out_size)
{
    (void)in_sizes; (void)n_in; (void)out_size;
    const float* pc = (const float*)d_in[0];

    float *nx1, *nx2, *nx3, *f1, *f2;
    int* idxb;
    float *w0T, *w1T;
    float *w2hi, *w2lo, *w3hi, *w3lo, *w4hi, *w4lo, *w5hi, *w5lo;
    float *b0, *b1, *b2, *b3, *b4, *b5;
    cudaGetSymbolAddress((void**)&nx1, g_nx1);
    cudaGetSymbolAddress((void**)&nx2, g_nx2);
    cudaGetSymbolAddress((void**)&nx3, g_nx3);
    cudaGetSymbolAddress((void**)&idxb, g_idxbuf);
    cudaGetSymbolAddress((void**)&f1, g_f1);
    cudaGetSymbolAddress((void**)&f2, g_f2);
    cudaGetSymbolAddress((void**)&w0T, g_w0T); cudaGetSymbolAddress((void**)&b0, g_b0);
    cudaGetSymbolAddress((void**)&w1T, g_w1T); cudaGetSymbolAddress((void**)&b1, g_b1);
    cudaGetSymbolAddress((void**)&w2hi, g_w2hi); cudaGetSymbolAddress((void**)&w2lo, g_w2lo);
    cudaGetSymbolAddress((void**)&b2, g_b2);
    cudaGetSymbolAddress((void**)&w3hi, g_w3hi); cudaGetSymbolAddress((void**)&w3lo, g_w3lo);
    cudaGetSymbolAddress((void**)&b3, g_b3);
    cudaGetSymbolAddress((void**)&w4hi, g_w4hi); cudaGetSymbolAddress((void**)&w4lo, g_w4lo);
    cudaGetSymbolAddress((void**)&b4, g_b4);
    cudaGetSymbolAddress((void**)&w5hi, g_w5hi); cudaGetSymbolAddress((void**)&w5lo, g_w5lo);
    cudaGetSymbolAddress((void**)&b5, g_b5);

    FoldArgs fa;
    const int cins[6]  = {9, 32, 67, 128, 131, 256};
    const int kps[6]   = {6, 32, 72, 128, 136, 256};
    const int couts[6] = {32, 64, 128, 128, 256, 256};
    float* wTs[6]  = {w0T, w1T, w2hi, w3hi, w4hi, w5hi};
    float* wLos[6] = {nullptr, nullptr, w2lo, w3lo, w4lo, w5lo};
    float* bss[6]  = {b0, b1, b2, b3, b4, b5};
    for (int l = 0; l < 6; l++) {
        fa.w[l]  = (const float*)d_in[1 + 5 * l];
        fa.g[l]  = (const float*)d_in[2 + 5 * l];
        fa.be[l] = (const float*)d_in[3 + 5 * l];
        fa.rm[l] = (const float*)d_in[4 + 5 * l];
        fa.rv[l] = (const float*)d_in[5 + 5 * l];
        fa.wT[l] = wTs[l]; fa.wLo[l] = wLos[l]; fa.bias[l] = bss[l];
        fa.cin[l] = cins[l]; fa.kp[l] = kps[l]; fa.cout[l] = couts[l];
    }
    fold_all_kernel<<<dim3(72, 6), 256>>>(fa);

    const float rr0 = (float)(0.02 * 0.02);
    const float rr1 = (float)(0.04 * 0.04);
    const float rr2 = (float)(0.08 * 0.08);

    // smem sizes (bytes)
    const int smem0 = ((6 + 32) * 132 + 512) * 4;                  // 22112
    const int smem1 = (128 * 76 + 128 * 132 + 128) * 4;            // 106,  -> 106960? computed: (9728+16896+128)*4 = 107008
    const int smem2 = (128 * 140 + 128 * 260 + 128) * 4;           // (17920+33280+128)*4 = 205312

    auto k0 = sa_mlp0_kernel<6, 32, 64, 32, 4, 128, 8, 16>;
    // stage1: C0=128,C1=128,CF=64,K0P=72,NS=32,KP=76,MP=132
    auto k1 = sa_gemm_kernel<128, 128, 64, 72, 32, 76, 132, false>;
    // stage2: C0=256,C1=256,CF=128,K0P=136,NS=16,KP=140,MP=260
    auto k2 = sa_gemm_kernel<256, 256, 128, 136, 16, 140, 260, true>;

    cudaFuncSetAttribute((const void*)k1, cudaFuncAttributeMaxDynamicSharedMemorySize, smem1);
    cudaFuncSetAttribute((const void*)k2, cudaFuncAttributeMaxDynamicSharedMemorySize, smem2);

    // ---- stage 0: N=4096 -> S=128 ----
    fps_kernel<4096, 128, 256><<<B, 256>>>(pc, nx1);
    ballquery_kernel<32><<<(B * S0) / 4, 128>>>(nx1, pc, idxb, N0, S0, rr0);
    k0<<<(B * S0) / 4, 128, smem0>>>(pc, nx1, idxb, w0T, b0, w1T, b1, f1, N0, S0);

    // ---- stage 1: N=128 -> S=64 (NG=4 groups/block -> 16 blocks/batch) ----
    fps_kernel<128, 64, 128><<<B, 128>>>(nx1, nx2);
    ballquery_kernel<32><<<(B * S1) / 4, 128>>>(nx2, nx1, idxb, S0, S1, rr1);
    k1<<<B * (S1 / 4), 256, smem1>>>(nx1, f1, nx2, idxb,
                                     w2hi, w2lo, b2, w3hi, w3lo, b3, f2, S0, S1);

    // ---- stage 2: N=64 -> S=32 (NG=8 groups/block -> 4 blocks/batch) ----
    fps_kernel<64, 32, 64><<<B, 64>>>(nx2, nx3);
    ballquery_kernel<16><<<(B * S2) / 4, 128>>>(nx3, nx2, idxb, S1, S2, rr2);
    k2<<<B * (S2 / 8), 256, smem2>>>(nx2, f2, nx3, idxb,
                                     w4hi, w4lo, b4, w5hi, w5lo, b5,
                                     (float*)d_out, S1, S2);
}

// round 16
// speedup vs baseline: 1.3165x; 1.1205x over previous
#include <cuda_runtime.h>
#include <cstdint>

// ---------------------------------------------------------------------------
// PointNet++ (3 SA stages), B=64, N=4096, fp32.
// Round 14: mma stage1/2 reshaped for occupancy: 64/32 samples per block
// (smem ~53/51 KB -> 3-4 blocks/SM), fragment-major pre-split tf32 weights
// (2x LDG.128 per A-fragment). Stage0 SIMT unchanged.
// ---------------------------------------------------------------------------

static constexpr int B   = 64;
static constexpr int N0  = 4096;
static constexpr int S0  = 128, NSAMP0 = 32;
static constexpr int S1  = 64;
static constexpr int S2  = 32;

// ------------------------- device scratch (no allocs) ----------------------
__device__ float g_nx1[B * S0 * 3];
__device__ float g_nx2[B * S1 * 3];
__device__ float g_nx3[B * S2 * 3];
__device__ int   g_idxbuf[B * S0 * NSAMP0];
__device__ __align__(16) float g_f1[B * S0 * 64];     // stage0 out, (B,S0,64)
__device__ __align__(16) float g_f2[B * S1 * 128];    // stage1 out, (B,S1,128)

// stage0 (SIMT): k-major folded weights, CIN folded 9->6
__device__ __align__(16) float g_w0T[6 * 32];     __device__ __align__(16) float g_b0[32];
__device__ __align__(16) float g_w1T[32 * 64];    __device__ __align__(16) float g_b1[64];
// stage1/2 (mma): FRAGMENT-MAJOR tf32 hi/lo pre-split, cols = [feat|xyz|pad]
__device__ __align__(16) float g_w2hi[128 * 72];  __device__ __align__(16) float g_w2lo[128 * 72];
__device__ __align__(16) float g_b2[128];
__device__ __align__(16) float g_w3hi[128 * 128]; __device__ __align__(16) float g_w3lo[128 * 128];
__device__ __align__(16) float g_b3[128];
__device__ __align__(16) float g_w4hi[256 * 136]; __device__ __align__(16) float g_w4lo[256 * 136];
__device__ __align__(16) float g_b4[256];
__device__ __align__(16) float g_w5hi[256 * 256]; __device__ __align__(16) float g_w5lo[256 * 256];
__device__ __align__(16) float g_b5[256];

// ------------------------- f32x2 helpers (stage0 SIMT) ---------------------
typedef unsigned long long u64;

__device__ __forceinline__ u64 pack2(float x) {
    u64 r;
    asm("mov.b64 %0, {%1, %2};" : "=l"(r) : "f"(x), "f"(x));
    return r;
}
__device__ __forceinline__ void unpack2(u64 v, float& lo, float& hi) {
    asm("mov.b64 {%0, %1}, %2;" : "=f"(lo), "=f"(hi) : "l"(v));
}
__device__ __forceinline__ u64 ffma2(u64 a, u64 b, u64 c) {
    u64 d;
    asm("fma.rn.f32x2 %0, %1, %2, %3;" : "=l"(d) : "l"(a), "l"(b), "l"(c));
    return d;
}

// ------------------------- tf32 helpers ------------------------------------
__device__ __forceinline__ void split_tf32(float x, uint32_t& hi, uint32_t& lo) {
    asm("cvt.rna.tf32.f32 %0, %1;" : "=r"(hi) : "f"(x));
    float hif = __uint_as_float(hi);
    float lof = __fsub_rn(x, hif);
    asm("cvt.rna.tf32.f32 %0, %1;" : "=r"(lo) : "f"(lof));
}
__device__ __forceinline__ void mma_tf32(float* c, const uint32_t* a, const uint32_t* b) {
    asm("mma.sync.aligned.m16n8k8.row.col.f32.tf32.tf32.f32 "
        "{%0,%1,%2,%3}, {%4,%5,%6,%7}, {%8,%9}, {%0,%1,%2,%3};"
        : "+f"(c[0]), "+f"(c[1]), "+f"(c[2]), "+f"(c[3])
        : "r"(a[0]), "r"(a[1]), "r"(a[2]), "r"(a[3]), "r"(b[0]), "r"(b[1]));
}

// ------------------------- merged BN fold ----------------------------------
// mma layers (l>=2): fragment-major layout. Element (o,k) of the o x KP
// matrix goes to tile (o/16, k/8), lane = (o%8)*4 + (k%4),
// i = (o%16)/8 | ((k%8)/4)<<1 -> dst = (tile*32 + lane)*4 + i.
// A-fragment load in the kernel = one uint4 per (mt, ks) per lane.
struct FoldArgs {
    const float* w[6]; const float* g[6]; const float* be[6];
    const float* rm[6]; const float* rv[6];
    float* wT[6];      // fp32 k-major (l0,l1) or tf32 hi frag-major (l2..5)
    float* wLo[6];     // tf32 lo frag-major (l2..5)
    float* bias[6];
    int cin[6]; int kp[6]; int cout[6];
};

__global__ void fold_all_kernel(FoldArgs a)
{
    int l = blockIdx.y;
    int cin = a.cin[l], KP = a.kp[l], cout = a.cout[l];
    const float* w = a.w[l]; const float* g = a.g[l]; const float* be = a.be[l];
    const float* rm = a.rm[l]; const float* rv = a.rv[l];
    float* wT = a.wT[l]; float* wLo = a.wLo[l]; float* bias = a.bias[l];
    int i = blockIdx.x * blockDim.x + threadIdx.x;
    if (i < cout) {
        float s = g[i] * rsqrtf(rv[i] + 1e-5f);
        bias[i] = be[i] - s * rm[i];
    }
    if (l == 0) {
        int tot = cout * 6;
        for (int e = i; e < tot; e += gridDim.x * blockDim.x) {
            int o = e / 6, k = e - o * 6;
            float s = g[o] * rsqrtf(rv[o] + 1e-5f);
            float val = (k < 3) ? w[o * 9 + k] : (w[o * 9 + k] + w[o * 9 + k + 3]);
            wT[k * cout + o] = val * s;
        }
    } else if (l == 1) {
        int tot = cout * cin;
        for (int e = i; e < tot; e += gridDim.x * blockDim.x) {
            int o = e / cin, k = e - o * cin;
            float s = g[o] * rsqrtf(rv[o] + 1e-5f);
            wT[k * cout + o] = w[e] * s;
        }
    } else {
        bool reord = (l == 2 || l == 4);
        int CF = cin - 3;
        int KT = KP >> 3;
        int tot = cout * KP;
        for (int e = i; e < tot; e += gridDim.x * blockDim.x) {
            int o = e / KP, k = e - o * KP;
            float s = g[o] * rsqrtf(rv[o] + 1e-5f);
            float val = 0.0f;
            if (reord) {
                int ko = (k < CF) ? (3 + k) : ((k < CF + 3) ? (k - CF) : -1);
                if (ko >= 0) val = w[o * cin + ko] * s;
            } else {
                if (k < cin) val = w[o * cin + k] * s;
            }
            uint32_t hi, lo;
            split_tf32(val, hi, lo);
            int r = o & 15, c = k & 7;
            int lane = (r & 7) * 4 + (c & 3);
            int ii = (r >> 3) | ((c >> 2) << 1);
            int dst = (((o >> 4) * KT + (k >> 3)) * 32 + lane) * 4 + ii;
            wT[dst]  = __uint_as_float(hi);
            wLo[dst] = __uint_as_float(lo);
        }
    }
}

// ------------------------- farthest point sampling -------------------------
template<int N, int NPOINT, int T>
__global__ void __launch_bounds__(T) fps_kernel(const float* __restrict__ xyz,
                                                float* __restrict__ newxyz)
{
    constexpr int PPT = N / T;
    int b = blockIdx.x;
    int tid = threadIdx.x;
    const float* x = xyz + (size_t)b * N * 3;

    float px[PPT], py[PPT], pz[PPT], dist[PPT];
#pragma unroll
    for (int i = 0; i < PPT; i++) {
        int p = tid + i * T;
        px[i] = x[p * 3 + 0];
        py[i] = x[p * 3 + 1];
        pz[i] = x[p * 3 + 2];
        dist[i] = 1e10f;
    }

    __shared__ float cur[3];
    __shared__ float wv[T / 32];
    __shared__ int   wi[T / 32];

    if (tid == 0) {
        cur[0] = x[0]; cur[1] = x[1]; cur[2] = x[2];
        float* o = newxyz + (size_t)b * NPOINT * 3;
        o[0] = x[0]; o[1] = x[1]; o[2] = x[2];
    }
    __syncthreads();

    for (int j = 1; j < NPOINT; j++) {
        float cx = cur[0], cy = cur[1], cz = cur[2];
        float bv = -1.0f;
        int   bi = 0x7fffffff;
#pragma unroll
        for (int i = 0; i < PPT; i++) {
            float dx = px[i] - cx, dy = py[i] - cy, dz = pz[i] - cz;
            float d = __fadd_rn(__fadd_rn(__fmul_rn(dx, dx), __fmul_rn(dy, dy)),
                                __fmul_rn(dz, dz));
            float nd = fminf(dist[i], d);
            dist[i] = nd;
            int gidx = tid + i * T;
            if (nd > bv || (nd == bv && gidx < bi)) { bv = nd; bi = gidx; }
        }
#pragma unroll
        for (int off = 16; off > 0; off >>= 1) {
            float ov = __shfl_down_sync(0xffffffffu, bv, off);
            int   oi = __shfl_down_sync(0xffffffffu, bi, off);
            if (ov > bv || (ov == bv && oi < bi)) { bv = ov; bi = oi; }
        }
        if ((tid & 31) == 0) { wv[tid >> 5] = bv; wi[tid >> 5] = bi; }
        __syncthreads();
        if (tid < 32) {
            constexpr int NW = T / 32;
            bv = (tid < NW) ? wv[tid] : -2.0f;
            bi = (tid < NW) ? wi[tid] : 0x7fffffff;
#pragma unroll
            for (int off = 16; off > 0; off >>= 1) {
                float ov = __shfl_down_sync(0xffffffffu, bv, off);
                int   oi = __shfl_down_sync(0xffffffffu, bi, off);
                if (ov > bv || (ov == bv && oi < bi)) { bv = ov; bi = oi; }
            }
            if (tid == 0) {
                const float* p = x + (size_t)bi * 3;
                float nx = p[0], ny = p[1], nz = p[2];
                cur[0] = nx; cur[1] = ny; cur[2] = nz;
                float* o = newxyz + ((size_t)b * NPOINT + j) * 3;
                o[0] = nx; o[1] = ny; o[2] = nz;
            }
        }
        __syncthreads();
    }
}

// ------------------------- ball query --------------------------------------
template<int NS>
__global__ void ballquery_kernel(const float* __restrict__ newxyz,
                                 const float* __restrict__ xyz,
                                 int* __restrict__ idxout,
                                 int N, int S, float rr)
{
    __shared__ int rows[4][NS];
    int lane = threadIdx.x & 31;
    int wip  = threadIdx.x >> 5;
    int q = blockIdx.x * 4 + wip;
    int b = q / S;
    const float* nq = newxyz + (size_t)q * 3;
    float qx = nq[0], qy = nq[1], qz = nq[2];
    const float* x = xyz + (size_t)b * N * 3;
    int* row = rows[wip];
    int cnt = 0;

    for (int base = 0; base < N; base += 32) {
        if (cnt >= NS) break;
        int p = base + lane;
        float dx = x[p * 3 + 0] - qx;
        float dy = x[p * 3 + 1] - qy;
        float dz = x[p * 3 + 2] - qz;
        float d = __fadd_rn(__fadd_rn(__fmul_rn(dx, dx), __fmul_rn(dy, dy)),
                            __fmul_rn(dz, dz));
        bool hit = d < rr;
        unsigned m = __ballot_sync(0xffffffffu, hit);
        if (hit) {
            int pos = cnt + __popc(m & ((1u << lane) - 1u));
            if (pos < NS) row[pos] = p;
        }
        cnt += __popc(m);
    }
    __syncwarp();
    int first = (cnt > 0) ? row[0] : 0;
    for (int t = cnt + lane; t < NS; t += 32) row[t] = first;
    __syncwarp();
    for (int t = lane; t < NS; t += 32) idxout[(size_t)q * NS + t] = row[t];
}

// ------------------------- stage0 SIMT MLP (proven config) ------------------
template<int CIN, int C0, int C1, int NS, int G, int T, int NO0, int NO1>
__global__ void __launch_bounds__(T) sa_mlp0_kernel(
    const float* __restrict__ xyz,
    const float* __restrict__ newxyz, const int* __restrict__ idx,
    const float* __restrict__ w0T, const float* __restrict__ b0,
    const float* __restrict__ w1T, const float* __restrict__ b1,
    float* __restrict__ out, int N, int S)
{
    constexpr int SB = NS * G;
    constexpr int LD = SB + 4;
    constexpr int CQ0 = C0 / 4, NGRP0 = SB / NO0;
    constexpr int CQ1 = C1 / 4, NGRP1 = SB / NO1;
    static_assert(CQ0 * NGRP0 == T, "layer0 mapping");
    static_assert(CQ1 * NGRP1 == T, "layer1 mapping");
    constexpr int OPG = NS / NO1;

    extern __shared__ __align__(16) float smem[];
    float* xs   = smem;
    float* mid  = xs + CIN * LD;
    float* pmax = mid + C0 * LD;

    int gs0 = blockIdx.x * G;
    int b = gs0 / S;
    int tid = threadIdx.x;

    int* sidx = (int*)pmax;
    for (int e = tid; e < SB; e += T)
        sidx[e] = idx[(size_t)(gs0 + e / NS) * NS + (e % NS)];
    __syncthreads();

    for (int e = tid; e < SB; e += T) {
        int g = e / NS;
        int id = sidx[e];
        const float* p = xyz + ((size_t)b * N + id) * 3;
        const float* c = newxyz + (size_t)(gs0 + g) * 3;
        float ax = p[0], ay = p[1], az = p[2];
        xs[0 * LD + e] = ax - c[0];
        xs[1 * LD + e] = ay - c[1];
        xs[2 * LD + e] = az - c[2];
        xs[3 * LD + e] = ax; xs[4 * LD + e] = ay; xs[5 * LD + e] = az;
    }
    __syncthreads();

    {
        int cq = tid % CQ0;
        int n8 = tid / CQ0;
        u64 acc[4][NO0 / 2];
        {
            float4 bv = *reinterpret_cast<const float4*>(b0 + 4 * cq);
            float bk[4] = {bv.x, bv.y, bv.z, bv.w};
#pragma unroll
            for (int i = 0; i < 4; i++) {
                u64 p = pack2(bk[i]);
#pragma unroll
                for (int j = 0; j < NO0 / 2; j++) acc[i][j] = p;
            }
        }
        const float* xrow = xs + n8 * NO0;
        const float* wptr = w0T + 4 * cq;
#pragma unroll 4
        for (int k = 0; k < CIN; k++) {
            float4 w = *reinterpret_cast<const float4*>(wptr + k * C0);
            ulonglong2 v[NO0 / 4];
            const ulonglong2* xr = reinterpret_cast<const ulonglong2*>(xrow + k * LD);
#pragma unroll
            for (int j = 0; j < NO0 / 4; j++) v[j] = xr[j];
            float wk[4] = {w.x, w.y, w.z, w.w};
#pragma unroll
            for (int i = 0; i < 4; i++) {
                u64 w2 = pack2(wk[i]);
#pragma unroll
                for (int j = 0; j < NO0 / 4; j++) {
                    acc[i][2 * j + 0] = ffma2(w2, v[j].x, acc[i][2 * j + 0]);
                    acc[i][2 * j + 1] = ffma2(w2, v[j].y, acc[i][2 * j + 1]);
                }
            }
        }
#pragma unroll
        for (int i = 0; i < 4; i++) {
            float* mrow = mid + (4 * cq + i) * LD + n8 * NO0;
#pragma unroll
            for (int j = 0; j < NO0 / 2; j++) {
                float lo, hi;
                unpack2(acc[i][j], lo, hi);
                float2 r;
                r.x = fmaxf(lo, 0.0f);
                r.y = fmaxf(hi, 0.0f);
                *reinterpret_cast<float2*>(mrow + 2 * j) = r;
            }
        }
    }
    __syncthreads();

    {
        int cq = tid % CQ1;
        int n8 = tid / CQ1;
        u64 acc[4][NO1 / 2];
        {
            float4 bv = *reinterpret_cast<const float4*>(b1 + 4 * cq);
            float bk[4] = {bv.x, bv.y, bv.z, bv.w};
#pragma unroll
            for (int i = 0; i < 4; i++) {
                u64 p = pack2(bk[i]);
#pragma unroll
                for (int j = 0; j < NO1 / 2; j++) acc[i][j] = p;
            }
        }
        const float* mrowb = mid + n8 * NO1;
        const float* wptr = w1T + 4 * cq;
#pragma unroll 4
        for (int k = 0; k < C0; k++) {
            float4 w = *reinterpret_cast<const float4*>(wptr + k * C1);
            ulonglong2 v[NO1 / 4];
            const ulonglong2* mr = reinterpret_cast<const ulonglong2*>(mrowb + k * LD);
#pragma unroll
            for (int j = 0; j < NO1 / 4; j++) v[j] = mr[j];
            float wk[4] = {w.x, w.y, w.z, w.w};
#pragma unroll
            for (int i = 0; i < 4; i++) {
                u64 w2 = pack2(wk[i]);
#pragma unroll
                for (int j = 0; j < NO1 / 4; j++) {
                    acc[i][2 * j + 0] = ffma2(w2, v[j].x, acc[i][2 * j + 0]);
                    acc[i][2 * j + 1] = ffma2(w2, v[j].y, acc[i][2 * j + 1]);
                }
            }
        }
#pragma unroll
        for (int i = 0; i < 4; i++) {
            float m = -3.4e38f;
#pragma unroll
            for (int j = 0; j < NO1 / 2; j++) {
                float lo, hi;
                unpack2(acc[i][j], lo, hi);
                m = fmaxf(m, fmaxf(lo, hi));
            }
            pmax[n8 * C1 + 4 * cq + i] = m;
        }
    }
    __syncthreads();

    for (int e = tid; e < G * C1; e += T) {
        int g = e / C1, ch = e - g * C1;
        float m = pmax[(g * OPG) * C1 + ch];
#pragma unroll
        for (int j = 1; j < OPG; j++)
            m = fmaxf(m, pmax[(g * OPG + j) * C1 + ch]);
        m = fmaxf(m, 0.0f);
        int gs = gs0 + g;
        out[(size_t)gs * C1 + ch] = m;                      // (B, S, C)
    }
}

// ------------------------- stage1/2 batched mma GEMM (v2) -------------------
// One block = SAMP samples (NG groups), 256 threads = 8 warps.
// Sample-major smem xs[sample][k] pitch KP, mid pitch MP (pitch%32==12 or 4
// -> conflict-free B LDS). A-fragments: ONE uint4 LDG per (mt,ks) per lane
// from fragment-major pre-split weights. 3xTF32 accumulation.
template<int C0, int C1, int CF, int K0P, int NS, int SAMP, int KP, int MP,
         bool FINAL>
__global__ void __launch_bounds__(256) sa_gemm_kernel(
    const float* __restrict__ xyz, const float* __restrict__ feats,
    const float* __restrict__ newxyz, const int* __restrict__ idx,
    const float* __restrict__ w0hi, const float* __restrict__ w0lo,
    const float* __restrict__ b0v,
    const float* __restrict__ w1hi, const float* __restrict__ w1lo,
    const float* __restrict__ b1v,
    float* __restrict__ out, int N, int S)
{
    constexpr int K0  = CF + 3;
    constexpr int NG  = SAMP / NS;     // groups per block
    constexpr int NSG = NS / 8;        // n8 tiles per group
    constexpr int TT  = SAMP / 8;      // n8 tiles per block
    constexpr int MT0 = C0 / 128;      // m16 tiles per warp
    constexpr int MT1 = C1 / 128;
    constexpr int K0S = K0P / 8;
    constexpr int K1S = C0 / 8;
    constexpr int CF4 = CF / 4;

    extern __shared__ __align__(16) float smem[];
    float* xs  = smem;                  // SAMP * KP
    float* mid = xs + SAMP * KP;        // SAMP * MP
    int*  sidx = (int*)(mid + SAMP * MP);

    int NT = S / NG;                    // blocks per batch
    int bt = blockIdx.x;
    int b  = bt / NT, nt = bt - b * NT;
    int gs0 = b * S + nt * NG;

    int tid  = threadIdx.x;
    int lane = tid & 31, warp = tid >> 5;
    int gid  = lane >> 2, tl = lane & 3;

    // ---- gather ----
    for (int e = tid; e < SAMP; e += 256)
        sidx[e] = idx[(size_t)(gs0 + e / NS) * NS + (e % NS)];
    __syncthreads();

    for (int e = tid; e < SAMP * CF4; e += 256) {
        int n = e / CF4, c4 = e - n * CF4;
        float4 v = reinterpret_cast<const float4*>(feats)[((size_t)b * N + sidx[n]) * CF4 + c4];
        *reinterpret_cast<float4*>(xs + n * KP + 4 * c4) = v;
    }
    for (int e = tid; e < SAMP; e += 256) {
        const float* p = xyz + ((size_t)b * N + sidx[e]) * 3;
        const float* c = newxyz + (size_t)(gs0 + e / NS) * 3;
        xs[e * KP + CF + 0] = p[0] - c[0];
        xs[e * KP + CF + 1] = p[1] - c[1];
        xs[e * KP + CF + 2] = p[2] - c[2];
    }
    for (int e = tid; e < (K0P - K0) * SAMP; e += 256) {
        int r = e / SAMP, n = e - r * SAMP;
        xs[n * KP + K0 + r] = 0.0f;
    }
    __syncthreads();

    const uint4* w0h4 = reinterpret_cast<const uint4*>(w0hi);
    const uint4* w0l4 = reinterpret_cast<const uint4*>(w0lo);
    const uint4* w1h4 = reinterpret_cast<const uint4*>(w1hi);
    const uint4* w1l4 = reinterpret_cast<const uint4*>(w1lo);

    // ---- layer 0: mid = relu(W0 @ X + b0) ----
    {
        float acc[MT0][TT][4];
#pragma unroll
        for (int mt = 0; mt < MT0; mt++) {
            int r0 = warp * MT0 * 16 + mt * 16 + gid;
            float bb0 = b0v[r0], bb1 = b0v[r0 + 8];
#pragma unroll
            for (int t = 0; t < TT; t++) {
                acc[mt][t][0] = bb0; acc[mt][t][1] = bb0;
                acc[mt][t][2] = bb1; acc[mt][t][3] = bb1;
            }
        }
#pragma unroll 1
        for (int ks = 0; ks < K0S; ks++) {
            uint32_t ah[MT0][4], al[MT0][4];
#pragma unroll
            for (int mt = 0; mt < MT0; mt++) {
                int tile = (warp * MT0 + mt) * K0S + ks;
                uint4 hv = w0h4[tile * 32 + lane];
                ah[mt][0] = hv.x; ah[mt][1] = hv.y; ah[mt][2] = hv.z; ah[mt][3] = hv.w;
                uint4 lv = w0l4[tile * 32 + lane];
                al[mt][0] = lv.x; al[mt][1] = lv.y; al[mt][2] = lv.z; al[mt][3] = lv.w;
            }
#pragma unroll
            for (int t = 0; t < TT; t++) {
                int col = t * 8 + gid;
                const float* xp = xs + col * KP + ks * 8 + tl;
                uint32_t bh[2], bl[2];
                split_tf32(xp[0], bh[0], bl[0]);
                split_tf32(xp[4], bh[1], bl[1]);
#pragma unroll
                for (int mt = 0; mt < MT0; mt++) {
                    mma_tf32(acc[mt][t], ah[mt], bl);
                    mma_tf32(acc[mt][t], al[mt], bh);
                    mma_tf32(acc[mt][t], ah[mt], bh);
                }
            }
        }
#pragma unroll
        for (int mt = 0; mt < MT0; mt++) {
            int r0 = warp * MT0 * 16 + mt * 16 + gid;
#pragma unroll
            for (int t = 0; t < TT; t++) {
                int colb = t * 8 + 2 * tl;
                mid[(colb + 0) * MP + r0]     = fmaxf(acc[mt][t][0], 0.0f);
                mid[(colb + 1) * MP + r0]     = fmaxf(acc[mt][t][1], 0.0f);
                mid[(colb + 0) * MP + r0 + 8] = fmaxf(acc[mt][t][2], 0.0f);
                mid[(colb + 1) * MP + r0 + 8] = fmaxf(acc[mt][t][3], 0.0f);
            }
        }
    }
    __syncthreads();

    // ---- layer 1 + maxpool ----
    {
        float acc[MT1][TT][4];
#pragma unroll
        for (int mt = 0; mt < MT1; mt++) {
            int r0 = warp * MT1 * 16 + mt * 16 + gid;
            float bb0 = b1v[r0], bb1 = b1v[r0 + 8];
#pragma unroll
            for (int t = 0; t < TT; t++) {
                acc[mt][t][0] = bb0; acc[mt][t][1] = bb0;
                acc[mt][t][2] = bb1; acc[mt][t][3] = bb1;
            }
        }
#pragma unroll 1
        for (int ks = 0; ks < K1S; ks++) {
            uint32_t ah[MT1][4], al[MT1][4];
#pragma unroll
            for (int mt = 0; mt < MT1; mt++) {
                int tile = (warp * MT1 + mt) * K1S + ks;
                uint4 hv = w1h4[tile * 32 + lane];
                ah[mt][0] = hv.x; ah[mt][1] = hv.y; ah[mt][2] = hv.z; ah[mt][3] = hv.w;
                uint4 lv = w1l4[tile * 32 + lane];
                al[mt][0] = lv.x; al[mt][1] = lv.y; al[mt][2] = lv.z; al[mt][3] = lv.w;
            }
#pragma unroll
            for (int t = 0; t < TT; t++) {
                int col = t * 8 + gid;
                const float* xp = mid + col * MP + ks * 8 + tl;
                uint32_t bh[2], bl[2];
                split_tf32(xp[0], bh[0], bl[0]);
                split_tf32(xp[4], bh[1], bl[1]);
#pragma unroll
                for (int mt = 0; mt < MT1; mt++) {
                    mma_tf32(acc[mt][t], ah[mt], bl);
                    mma_tf32(acc[mt][t], al[mt], bh);
                    mma_tf32(acc[mt][t], ah[mt], bh);
                }
            }
        }
        // maxpool per group + relu + store
#pragma unroll
        for (int mt = 0; mt < MT1; mt++) {
            int r0 = warp * MT1 * 16 + mt * 16 + gid;
#pragma unroll
            for (int gl = 0; gl < NG; gl++) {
                float m0 = -3.4e38f, m1 = -3.4e38f;
#pragma unroll
                for (int tt = 0; tt < NSG; tt++) {
                    int t = gl * NSG + tt;
                    m0 = fmaxf(m0, fmaxf(acc[mt][t][0], acc[mt][t][1]));
                    m1 = fmaxf(m1, fmaxf(acc[mt][t][2], acc[mt][t][3]));
                }
                m0 = fmaxf(m0, __shfl_xor_sync(0xffffffffu, m0, 1));
                m0 = fmaxf(m0, __shfl_xor_sync(0xffffffffu, m0, 2));
                m1 = fmaxf(m1, __shfl_xor_sync(0xffffffffu, m1, 1));
                m1 = fmaxf(m1, __shfl_xor_sync(0xffffffffu, m1, 2));
                if (tl == 0) {
                    int gs = gs0 + gl;
                    int s  = gs - b * S;
                    float v0 = fmaxf(m0, 0.0f);
                    float v1 = fmaxf(m1, 0.0f);
                    if (FINAL) {
                        out[(size_t)b * C1 * S + (size_t)r0 * S + s]       = v0;
                        out[(size_t)b * C1 * S + (size_t)(r0 + 8) * S + s] = v1;
                    } else {
                        out[(size_t)gs * C1 + r0]     = v0;
                        out[(size_t)gs * C1 + r0 + 8] = v1;
                    }
                }
            }
        }
    }
}

// ---------------------------------------------------------------------------
extern "C" void kernel_launch(void* const* d_in, const int* in_sizes, int n_in,
                              void* d_out, int out_size)
{
    (void)in_sizes; (void)n_in; (void)out_size;
    const float* pc = (const float*)d_in[0];

    float *nx1, *nx2, *nx3, *f1, *f2;
    int* idxb;
    float *w0T, *w1T;
    float *w2hi, *w2lo, *w3hi, *w3lo, *w4hi, *w4lo, *w5hi, *w5lo;
    float *b0, *b1, *b2, *b3, *b4, *b5;
    cudaGetSymbolAddress((void**)&nx1, g_nx1);
    cudaGetSymbolAddress((void**)&nx2, g_nx2);
    cudaGetSymbolAddress((void**)&nx3, g_nx3);
    cudaGetSymbolAddress((void**)&idxb, g_idxbuf);
    cudaGetSymbolAddress((void**)&f1, g_f1);
    cudaGetSymbolAddress((void**)&f2, g_f2);
    cudaGetSymbolAddress((void**)&w0T, g_w0T); cudaGetSymbolAddress((void**)&b0, g_b0);
    cudaGetSymbolAddress((void**)&w1T, g_w1T); cudaGetSymbolAddress((void**)&b1, g_b1);
    cudaGetSymbolAddress((void**)&w2hi, g_w2hi); cudaGetSymbolAddress((void**)&w2lo, g_w2lo);
    cudaGetSymbolAddress((void**)&b2, g_b2);
    cudaGetSymbolAddress((void**)&w3hi, g_w3hi); cudaGetSymbolAddress((void**)&w3lo, g_w3lo);
    cudaGetSymbolAddress((void**)&b3, g_b3);
    cudaGetSymbolAddress((void**)&w4hi, g_w4hi); cudaGetSymbolAddress((void**)&w4lo, g_w4lo);
    cudaGetSymbolAddress((void**)&b4, g_b4);
    cudaGetSymbolAddress((void**)&w5hi, g_w5hi); cudaGetSymbolAddress((void**)&w5lo, g_w5lo);
    cudaGetSymbolAddress((void**)&b5, g_b5);

    FoldArgs fa;
    const int cins[6]  = {9, 32, 67, 128, 131, 256};
    const int kps[6]   = {6, 32, 72, 128, 136, 256};
    const int couts[6] = {32, 64, 128, 128, 256, 256};
    float* wTs[6]  = {w0T, w1T, w2hi, w3hi, w4hi, w5hi};
    float* wLos[6] = {nullptr, nullptr, w2lo, w3lo, w4lo, w5lo};
    float* bss[6]  = {b0, b1, b2, b3, b4, b5};
    for (int l = 0; l < 6; l++) {
        fa.w[l]  = (const float*)d_in[1 + 5 * l];
        fa.g[l]  = (const float*)d_in[2 + 5 * l];
        fa.be[l] = (const float*)d_in[3 + 5 * l];
        fa.rm[l] = (const float*)d_in[4 + 5 * l];
        fa.rv[l] = (const float*)d_in[5 + 5 * l];
        fa.wT[l] = wTs[l]; fa.wLo[l] = wLos[l]; fa.bias[l] = bss[l];
        fa.cin[l] = cins[l]; fa.kp[l] = kps[l]; fa.cout[l] = couts[l];
    }
    fold_all_kernel<<<dim3(72, 6), 256>>>(fa);

    const float rr0 = (float)(0.02 * 0.02);
    const float rr1 = (float)(0.04 * 0.04);
    const float rr2 = (float)(0.08 * 0.08);

    // smem sizes (bytes)
    const int smem0 = ((6 + 32) * 132 + 512) * 4;              // 22112
    const int smem1 = (64 * 76 + 64 * 132 + 64) * 4;           // 53504
    const int smem2 = (32 * 140 + 32 * 260 + 32) * 4;          // 51328

    auto k0 = sa_mlp0_kernel<6, 32, 64, 32, 4, 128, 8, 16>;
    // stage1: C0=128,C1=128,CF=64,K0P=72,NS=32,SAMP=64,KP=76,MP=132
    auto k1 = sa_gemm_kernel<128, 128, 64, 72, 32, 64, 76, 132, false>;
    // stage2: C0=256,C1=256,CF=128,K0P=136,NS=16,SAMP=32,KP=140,MP=260
    auto k2 = sa_gemm_kernel<256, 256, 128, 136, 16, 32, 140, 260, true>;

    cudaFuncSetAttribute((const void*)k1, cudaFuncAttributeMaxDynamicSharedMemorySize, smem1);
    cudaFuncSetAttribute((const void*)k2, cudaFuncAttributeMaxDynamicSharedMemorySize, smem2);

    // ---- stage 0: N=4096 -> S=128 ----
    fps_kernel<4096, 128, 256><<<B, 256>>>(pc, nx1);
    ballquery_kernel<32><<<(B * S0) / 4, 128>>>(nx1, pc, idxb, N0, S0, rr0);
    k0<<<(B * S0) / 4, 128, smem0>>>(pc, nx1, idxb, w0T, b0, w1T, b1, f1, N0, S0);

    // ---- stage 1: N=128 -> S=64 (NG=2 -> 32 blocks/batch, 2048 blocks) ----
    fps_kernel<128, 64, 128><<<B, 128>>>(nx1, nx2);
    ballquery_kernel<32><<<(B * S1) / 4, 128>>>(nx2, nx1, idxb, S0, S1, rr1);
    k1<<<B * (S1 / 2), 256, smem1>>>(nx1, f1, nx2, idxb,
                                     w2hi, w2lo, b2, w3hi, w3lo, b3, f2, S0, S1);

    // ---- stage 2: N=64 -> S=32 (NG=2 -> 16 blocks/batch, 1024 blocks) ----
    fps_kernel<64, 32, 64><<<B, 64>>>(nx2, nx3);
    ballquery_kernel<16><<<(B * S2) / 4, 128>>>(nx3, nx2, idxb, S1, S2, rr2);
    k2<<<B * (S2 / 2), 256, smem2>>>(nx2, f2, nx3, idxb,
                                     w4hi, w4lo, b4, w5hi, w5lo, b5,
                                     (float*)d_out, S1, S2);
}

// round 17
// speedup vs baseline: 1.7160x; 1.3035x over previous
#include <cuda_runtime.h>
#include <cstdint>

// ---------------------------------------------------------------------------
// PointNet++ (3 SA stages), B=64, N=4096, fp32.
// Round 17: stage1/2 on bf16 tensor cores (m16n8k16, 3xBF16 split precision,
// all operands pre-split: weights at fold time, activations at gather /
// layer0-epilogue into bf16 hi/lo smem planes). Half the mma count of tf32,
// half the smem, 7-8 blocks/SM. Stage0 SIMT unchanged.
// ---------------------------------------------------------------------------

typedef unsigned short u16;
typedef unsigned int   u32;
typedef unsigned long long u64;

static constexpr int B   = 64;
static constexpr int N0  = 4096;
static constexpr int S0  = 128, NSAMP0 = 32;
static constexpr int S1  = 64;
static constexpr int S2  = 32;

// ------------------------- device scratch (no allocs) ----------------------
__device__ float g_nx1[B * S0 * 3];
__device__ float g_nx2[B * S1 * 3];
__device__ float g_nx3[B * S2 * 3];
__device__ int   g_idxbuf[B * S0 * NSAMP0];
__device__ __align__(16) float g_f1[B * S0 * 64];
__device__ __align__(16) float g_f2[B * S1 * 128];

// stage0 (SIMT): k-major folded fp32 weights, CIN folded 9->6
__device__ __align__(16) float g_w0T[6 * 32];     __device__ __align__(16) float g_b0[32];
__device__ __align__(16) float g_w1T[32 * 64];    __device__ __align__(16) float g_b1[64];
// stage1/2 (mma): fragment-major bf16 hi/lo pre-split, cols = [feat|xyz|pad]
__device__ __align__(16) u16 g_w2hi[128 * 80];   __device__ __align__(16) u16 g_w2lo[128 * 80];
__device__ __align__(16) float g_b2[128];
__device__ __align__(16) u16 g_w3hi[128 * 128];  __device__ __align__(16) u16 g_w3lo[128 * 128];
__device__ __align__(16) float g_b3[128];
__device__ __align__(16) u16 g_w4hi[256 * 144];  __device__ __align__(16) u16 g_w4lo[256 * 144];
__device__ __align__(16) float g_b4[256];
__device__ __align__(16) u16 g_w5hi[256 * 256];  __device__ __align__(16) u16 g_w5lo[256 * 256];
__device__ __align__(16) float g_b5[256];

// ------------------------- f32x2 helpers (stage0 SIMT) ---------------------
__device__ __forceinline__ u64 pack2(float x) {
    u64 r;
    asm("mov.b64 %0, {%1, %2};" : "=l"(r) : "f"(x), "f"(x));
    return r;
}
__device__ __forceinline__ void unpack2(u64 v, float& lo, float& hi) {
    asm("mov.b64 {%0, %1}, %2;" : "=f"(lo), "=f"(hi) : "l"(v));
}
__device__ __forceinline__ u64 ffma2(u64 a, u64 b, u64 c) {
    u64 d;
    asm("fma.rn.f32x2 %0, %1, %2, %3;" : "=l"(d) : "l"(a), "l"(b), "l"(c));
    return d;
}

// ------------------------- bf16 helpers ------------------------------------
__device__ __forceinline__ u16 f2bf(float x) {
    u16 r;
    asm("cvt.rn.bf16.f32 %0, %1;" : "=h"(r) : "f"(x));
    return r;
}
__device__ __forceinline__ float bf2f(u16 h) {
    float r;
    asm("cvt.f32.bf16 %0, %1;" : "=f"(r) : "h"(h));
    return r;
}
__device__ __forceinline__ void split_bf16(float x, u16& hi, u16& lo) {
    hi = f2bf(x);
    float r = __fsub_rn(x, bf2f(hi));
    lo = f2bf(r);
}
__device__ __forceinline__ u32 pk16(u16 a, u16 b) {
    return (u32)a | ((u32)b << 16);
}
__device__ __forceinline__ void mma_bf16(float* c, const u32* a, const u32* b) {
    asm("mma.sync.aligned.m16n8k16.row.col.f32.bf16.bf16.f32 "
        "{%0,%1,%2,%3}, {%4,%5,%6,%7}, {%8,%9}, {%0,%1,%2,%3};"
        : "+f"(c[0]), "+f"(c[1]), "+f"(c[2]), "+f"(c[3])
        : "r"(a[0]), "r"(a[1]), "r"(a[2]), "r"(a[3]), "r"(b[0]), "r"(b[1]));
}

// ------------------------- merged BN fold ----------------------------------
// mma layers: fragment-major m16n8k16 layout. Element (o,k):
// tile = (o/16)*(KP/16) + k/16; lane = (o%8)*4 + ((k%8)>>1);
// reg i = ((o%16)>>3) + 2*((k%16)>>3); half = k&1.
// dst u16 index = ((tile*32 + lane)*4 + i)*2 + half.
struct FoldArgs {
    const float* w[6]; const float* g[6]; const float* be[6];
    const float* rm[6]; const float* rv[6];
    float* wT[2];           // l0,l1 fp32 k-major
    u16* wHi[6]; u16* wLo[6];
    float* bias[6];
    int cin[6]; int kp[6]; int cout[6];
};

__global__ void fold_all_kernel(FoldArgs a)
{
    int l = blockIdx.y;
    int cin = a.cin[l], KP = a.kp[l], cout = a.cout[l];
    const float* w = a.w[l]; const float* g = a.g[l]; const float* be = a.be[l];
    const float* rm = a.rm[l]; const float* rv = a.rv[l];
    float* bias = a.bias[l];
    int i = blockIdx.x * blockDim.x + threadIdx.x;
    if (i < cout) {
        float s = g[i] * rsqrtf(rv[i] + 1e-5f);
        bias[i] = be[i] - s * rm[i];
    }
    if (l == 0) {
        float* wT = a.wT[0];
        int tot = cout * 6;
        for (int e = i; e < tot; e += gridDim.x * blockDim.x) {
            int o = e / 6, k = e - o * 6;
            float s = g[o] * rsqrtf(rv[o] + 1e-5f);
            float val = (k < 3) ? w[o * 9 + k] : (w[o * 9 + k] + w[o * 9 + k + 3]);
            wT[k * cout + o] = val * s;
        }
    } else if (l == 1) {
        float* wT = a.wT[1];
        int tot = cout * cin;
        for (int e = i; e < tot; e += gridDim.x * blockDim.x) {
            int o = e / cin, k = e - o * cin;
            float s = g[o] * rsqrtf(rv[o] + 1e-5f);
            wT[k * cout + o] = w[e] * s;
        }
    } else {
        u16* wHi = a.wHi[l]; u16* wLo = a.wLo[l];
        bool reord = (l == 2 || l == 4);
        int CF = cin - 3;
        int KT = KP >> 4;
        int tot = cout * KP;
        for (int e = i; e < tot; e += gridDim.x * blockDim.x) {
            int o = e / KP, k = e - o * KP;
            float s = g[o] * rsqrtf(rv[o] + 1e-5f);
            float val = 0.0f;
            if (reord) {
                int ko = (k < CF) ? (3 + k) : ((k < CF + 3) ? (k - CF) : -1);
                if (ko >= 0) val = w[o * cin + ko] * s;
            } else {
                if (k < cin) val = w[o * cin + k] * s;
            }
            u16 hi, lo;
            split_bf16(val, hi, lo);
            int r = o & 15, c = k & 15;
            int lane = (r & 7) * 4 + ((c & 7) >> 1);
            int ii = (r >> 3) + 2 * (c >> 3);
            int dst = (((((o >> 4) * KT) + (k >> 4)) * 32 + lane) * 4 + ii) * 2 + (k & 1);
            wHi[dst] = hi;
            wLo[dst] = lo;
        }
    }
}

// ------------------------- farthest point sampling -------------------------
template<int N, int NPOINT, int T>
__global__ void __launch_bounds__(T) fps_kernel(const float* __restrict__ xyz,
                                                float* __restrict__ newxyz)
{
    constexpr int PPT = N / T;
    int b = blockIdx.x;
    int tid = threadIdx.x;
    const float* x = xyz + (size_t)b * N * 3;

    float px[PPT], py[PPT], pz[PPT], dist[PPT];
#pragma unroll
    for (int i = 0; i < PPT; i++) {
        int p = tid + i * T;
        px[i] = x[p * 3 + 0];
        py[i] = x[p * 3 + 1];
        pz[i] = x[p * 3 + 2];
        dist[i] = 1e10f;
    }

    __shared__ float cur[3];
    __shared__ float wv[T / 32];
    __shared__ int   wi[T / 32];

    if (tid == 0) {
        cur[0] = x[0]; cur[1] = x[1]; cur[2] = x[2];
        float* o = newxyz + (size_t)b * NPOINT * 3;
        o[0] = x[0]; o[1] = x[1]; o[2] = x[2];
    }
    __syncthreads();

    for (int j = 1; j < NPOINT; j++) {
        float cx = cur[0], cy = cur[1], cz = cur[2];
        float bv = -1.0f;
        int   bi = 0x7fffffff;
#pragma unroll
        for (int i = 0; i < PPT; i++) {
            float dx = px[i] - cx, dy = py[i] - cy, dz = pz[i] - cz;
            float d = __fadd_rn(__fadd_rn(__fmul_rn(dx, dx), __fmul_rn(dy, dy)),
                                __fmul_rn(dz, dz));
            float nd = fminf(dist[i], d);
            dist[i] = nd;
            int gidx = tid + i * T;
            if (nd > bv || (nd == bv && gidx < bi)) { bv = nd; bi = gidx; }
        }
#pragma unroll
        for (int off = 16; off > 0; off >>= 1) {
            float ov = __shfl_down_sync(0xffffffffu, bv, off);
            int   oi = __shfl_down_sync(0xffffffffu, bi, off);
            if (ov > bv || (ov == bv && oi < bi)) { bv = ov; bi = oi; }
        }
        if ((tid & 31) == 0) { wv[tid >> 5] = bv; wi[tid >> 5] = bi; }
        __syncthreads();
        if (tid < 32) {
            constexpr int NW = T / 32;
            bv = (tid < NW) ? wv[tid] : -2.0f;
            bi = (tid < NW) ? wi[tid] : 0x7fffffff;
#pragma unroll
            for (int off = 16; off > 0; off >>= 1) {
                float ov = __shfl_down_sync(0xffffffffu, bv, off);
                int   oi = __shfl_down_sync(0xffffffffu, bi, off);
                if (ov > bv || (ov == bv && oi < bi)) { bv = ov; bi = oi; }
            }
            if (tid == 0) {
                const float* p = x + (size_t)bi * 3;
                float nx = p[0], ny = p[1], nz = p[2];
                cur[0] = nx; cur[1] = ny; cur[2] = nz;
                float* o = newxyz + ((size_t)b * NPOINT + j) * 3;
                o[0] = nx; o[1] = ny; o[2] = nz;
            }
        }
        __syncthreads();
    }
}

// ------------------------- ball query --------------------------------------
template<int NS>
__global__ void ballquery_kernel(const float* __restrict__ newxyz,
                                 const float* __restrict__ xyz,
                                 int* __restrict__ idxout,
                                 int N, int S, float rr)
{
    __shared__ int rows[4][NS];
    int lane = threadIdx.x & 31;
    int wip  = threadIdx.x >> 5;
    int q = blockIdx.x * 4 + wip;
    int b = q / S;
    const float* nq = newxyz + (size_t)q * 3;
    float qx = nq[0], qy = nq[1], qz = nq[2];
    const float* x = xyz + (size_t)b * N * 3;
    int* row = rows[wip];
    int cnt = 0;

    for (int base = 0; base < N; base += 32) {
        if (cnt >= NS) break;
        int p = base + lane;
        float dx = x[p * 3 + 0] - qx;
        float dy = x[p * 3 + 1] - qy;
        float dz = x[p * 3 + 2] - qz;
        float d = __fadd_rn(__fadd_rn(__fmul_rn(dx, dx), __fmul_rn(dy, dy)),
                            __fmul_rn(dz, dz));
        bool hit = d < rr;
        unsigned m = __ballot_sync(0xffffffffu, hit);
        if (hit) {
            int pos = cnt + __popc(m & ((1u << lane) - 1u));
            if (pos < NS) row[pos] = p;
        }
        cnt += __popc(m);
    }
    __syncwarp();
    int first = (cnt > 0) ? row[0] : 0;
    for (int t = cnt + lane; t < NS; t += 32) row[t] = first;
    __syncwarp();
    for (int t = lane; t < NS; t += 32) idxout[(size_t)q * NS + t] = row[t];
}

// ------------------------- stage0 SIMT MLP (proven config) ------------------
template<int CIN, int C0, int C1, int NS, int G, int T, int NO0, int NO1>
__global__ void __launch_bounds__(T) sa_mlp0_kernel(
    const float* __restrict__ xyz,
    const float* __restrict__ newxyz, const int* __restrict__ idx,
    const float* __restrict__ w0T, const float* __restrict__ b0,
    const float* __restrict__ w1T, const float* __restrict__ b1,
    float* __restrict__ out, int N, int S)
{
    constexpr int SB = NS * G;
    constexpr int LD = SB + 4;
    constexpr int CQ0 = C0 / 4, NGRP0 = SB / NO0;
    constexpr int CQ1 = C1 / 4, NGRP1 = SB / NO1;
    static_assert(CQ0 * NGRP0 == T, "layer0 mapping");
    static_assert(CQ1 * NGRP1 == T, "layer1 mapping");
    constexpr int OPG = NS / NO1;

    extern __shared__ __align__(16) float smem[];
    float* xs   = smem;
    float* mid  = xs + CIN * LD;
    float* pmax = mid + C0 * LD;

    int gs0 = blockIdx.x * G;
    int b = gs0 / S;
    int tid = threadIdx.x;

    int* sidx = (int*)pmax;
    for (int e = tid; e < SB; e += T)
        sidx[e] = idx[(size_t)(gs0 + e / NS) * NS + (e % NS)];
    __syncthreads();

    for (int e = tid; e < SB; e += T) {
        int g = e / NS;
        int id = sidx[e];
        const float* p = xyz + ((size_t)b * N + id) * 3;
        const float* c = newxyz + (size_t)(gs0 + g) * 3;
        float ax = p[0], ay = p[1], az = p[2];
        xs[0 * LD + e] = ax - c[0];
        xs[1 * LD + e] = ay - c[1];
        xs[2 * LD + e] = az - c[2];
        xs[3 * LD + e] = ax; xs[4 * LD + e] = ay; xs[5 * LD + e] = az;
    }
    __syncthreads();

    {
        int cq = tid % CQ0;
        int n8 = tid / CQ0;
        u64 acc[4][NO0 / 2];
        {
            float4 bv = *reinterpret_cast<const float4*>(b0 + 4 * cq);
            float bk[4] = {bv.x, bv.y, bv.z, bv.w};
#pragma unroll
            for (int i = 0; i < 4; i++) {
                u64 p = pack2(bk[i]);
#pragma unroll
                for (int j = 0; j < NO0 / 2; j++) acc[i][j] = p;
            }
        }
        const float* xrow = xs + n8 * NO0;
        const float* wptr = w0T + 4 * cq;
#pragma unroll 4
        for (int k = 0; k < CIN; k++) {
            float4 w = *reinterpret_cast<const float4*>(wptr + k * C0);
            ulonglong2 v[NO0 / 4];
            const ulonglong2* xr = reinterpret_cast<const ulonglong2*>(xrow + k * LD);
#pragma unroll
            for (int j = 0; j < NO0 / 4; j++) v[j] = xr[j];
            float wk[4] = {w.x, w.y, w.z, w.w};
#pragma unroll
            for (int i = 0; i < 4; i++) {
                u64 w2 = pack2(wk[i]);
#pragma unroll
                for (int j = 0; j < NO0 / 4; j++) {
                    acc[i][2 * j + 0] = ffma2(w2, v[j].x, acc[i][2 * j + 0]);
                    acc[i][2 * j + 1] = ffma2(w2, v[j].y, acc[i][2 * j + 1]);
                }
            }
        }
#pragma unroll
        for (int i = 0; i < 4; i++) {
            float* mrow = mid + (4 * cq + i) * LD + n8 * NO0;
#pragma unroll
            for (int j = 0; j < NO0 / 2; j++) {
                float lo, hi;
                unpack2(acc[i][j], lo, hi);
                float2 r;
                r.x = fmaxf(lo, 0.0f);
                r.y = fmaxf(hi, 0.0f);
                *reinterpret_cast<float2*>(mrow + 2 * j) = r;
            }
        }
    }
    __syncthreads();

    {
        int cq = tid % CQ1;
        int n8 = tid / CQ1;
        u64 acc[4][NO1 / 2];
        {
            float4 bv = *reinterpret_cast<const float4*>(b1 + 4 * cq);
            float bk[4] = {bv.x, bv.y, bv.z, bv.w};
#pragma unroll
            for (int i = 0; i < 4; i++) {
                u64 p = pack2(bk[i]);
#pragma unroll
                for (int j = 0; j < NO1 / 2; j++) acc[i][j] = p;
            }
        }
        const float* mrowb = mid + n8 * NO1;
        const float* wptr = w1T + 4 * cq;
#pragma unroll 4
        for (int k = 0; k < C0; k++) {
            float4 w = *reinterpret_cast<const float4*>(wptr + k * C1);
            ulonglong2 v[NO1 / 4];
            const ulonglong2* mr = reinterpret_cast<const ulonglong2*>(mrowb + k * LD);
#pragma unroll
            for (int j = 0; j < NO1 / 4; j++) v[j] = mr[j];
            float wk[4] = {w.x, w.y, w.z, w.w};
#pragma unroll
            for (int i = 0; i < 4; i++) {
                u64 w2 = pack2(wk[i]);
#pragma unroll
                for (int j = 0; j < NO1 / 4; j++) {
                    acc[i][2 * j + 0] = ffma2(w2, v[j].x, acc[i][2 * j + 0]);
                    acc[i][2 * j + 1] = ffma2(w2, v[j].y, acc[i][2 * j + 1]);
                }
            }
        }
#pragma unroll
        for (int i = 0; i < 4; i++) {
            float m = -3.4e38f;
#pragma unroll
            for (int j = 0; j < NO1 / 2; j++) {
                float lo, hi;
                unpack2(acc[i][j], lo, hi);
                m = fmaxf(m, fmaxf(lo, hi));
            }
            pmax[n8 * C1 + 4 * cq + i] = m;
        }
    }
    __syncthreads();

    for (int e = tid; e < G * C1; e += T) {
        int g = e / C1, ch = e - g * C1;
        float m = pmax[(g * OPG) * C1 + ch];
#pragma unroll
        for (int j = 1; j < OPG; j++)
            m = fmaxf(m, pmax[(g * OPG + j) * C1 + ch]);
        m = fmaxf(m, 0.0f);
        int gs = gs0 + g;
        out[(size_t)gs * C1 + ch] = m;                      // (B, S, C)
    }
}

// ------------------------- stage1/2 bf16 mma GEMM ---------------------------
// One block = SAMP samples, 256 threads = 8 warps. Activations in smem as
// bf16 hi/lo planes (sample-major, pitch ≡ 24 mod 64 elements ->
// conflict-free B LDS). Weights fragment-major pre-split bf16 hi/lo in
// global. 3xBF16: acc += Ahi*Blo + Alo*Bhi + Ahi*Bhi (fp32 accumulate).
template<int C0, int C1, int CF, int K0P, int NS, int SAMP, int KP2, int MP2,
         bool FINAL>
__global__ void __launch_bounds__(256) sa_gemm_kernel(
    const float* __restrict__ xyz, const float* __restrict__ feats,
    const float* __restrict__ newxyz, const int* __restrict__ idx,
    const u16* __restrict__ w0hi, const u16* __restrict__ w0lo,
    const float* __restrict__ b0v,
    const u16* __restrict__ w1hi, const u16* __restrict__ w1lo,
    const float* __restrict__ b1v,
    float* __restrict__ out, int N, int S)
{
    constexpr int K0  = CF + 3;
    constexpr int NG  = SAMP / NS;     // groups per block (>=1)
    constexpr int NSG = NS / 8;        // n8 tiles per group
    constexpr int TT  = SAMP / 8;      // n8 tiles per block
    constexpr int MT0 = C0 / 128;      // m16 tiles per warp
    constexpr int MT1 = C1 / 128;
    constexpr int K0S = K0P / 16;      // k16 steps
    constexpr int K1S = C0 / 16;
    constexpr int CF4 = CF / 4;
    constexpr int PADE = K0P - K0 - 1; // zero elements after (rz,0) pair

    extern __shared__ __align__(16) u16 smem16[];
    u16* xs_hi  = smem16;                        // SAMP * KP2
    u16* xs_lo  = xs_hi + SAMP * KP2;
    u16* mid_hi = xs_lo + SAMP * KP2;            // SAMP * MP2
    u16* mid_lo = mid_hi + SAMP * MP2;
    int* sidx   = (int*)(mid_lo + SAMP * MP2);

    int NT = S / NG;
    int bt = blockIdx.x;
    int b  = bt / NT, nt = bt - b * NT;
    int gs0 = b * S + nt * NG;

    int tid  = threadIdx.x;
    int lane = tid & 31, warp = tid >> 5;
    int gid  = lane >> 2, tl = lane & 3;

    // ---- gather ----
    for (int e = tid; e < SAMP; e += 256)
        sidx[e] = idx[(size_t)(gs0 + e / NS) * NS + (e % NS)];
    __syncthreads();

    for (int e = tid; e < SAMP * CF4; e += 256) {
        int n = e / CF4, c4 = e - n * CF4;
        float4 v = reinterpret_cast<const float4*>(feats)[((size_t)b * N + sidx[n]) * CF4 + c4];
        u16 h0, l0, h1, l1, h2, l2, h3, l3;
        split_bf16(v.x, h0, l0); split_bf16(v.y, h1, l1);
        split_bf16(v.z, h2, l2); split_bf16(v.w, h3, l3);
        int base = n * KP2 + 4 * c4;
        *(u32*)(xs_hi + base)     = pk16(h0, h1);
        *(u32*)(xs_hi + base + 2) = pk16(h2, h3);
        *(u32*)(xs_lo + base)     = pk16(l0, l1);
        *(u32*)(xs_lo + base + 2) = pk16(l2, l3);
    }
    for (int e = tid; e < SAMP; e += 256) {
        const float* p = xyz + ((size_t)b * N + sidx[e]) * 3;
        const float* c = newxyz + (size_t)(gs0 + e / NS) * 3;
        float rx = p[0] - c[0], ry = p[1] - c[1], rz = p[2] - c[2];
        u16 hx, lx, hy, ly, hz, lz;
        split_bf16(rx, hx, lx); split_bf16(ry, hy, ly); split_bf16(rz, hz, lz);
        int base = e * KP2 + CF;
        *(u32*)(xs_hi + base)     = pk16(hx, hy);
        *(u32*)(xs_hi + base + 2) = pk16(hz, 0);
        *(u32*)(xs_lo + base)     = pk16(lx, ly);
        *(u32*)(xs_lo + base + 2) = pk16(lz, 0);
    }
    for (int e = tid; e < SAMP * PADE; e += 256) {
        int n = e / PADE, j = e - n * PADE;
        xs_hi[n * KP2 + K0 + 1 + j] = 0;
        xs_lo[n * KP2 + K0 + 1 + j] = 0;
    }
    __syncthreads();

    const uint4* w0h4 = reinterpret_cast<const uint4*>(w0hi);
    const uint4* w0l4 = reinterpret_cast<const uint4*>(w0lo);
    const uint4* w1h4 = reinterpret_cast<const uint4*>(w1hi);
    const uint4* w1l4 = reinterpret_cast<const uint4*>(w1lo);

    // ---- layer 0: mid = relu(W0 @ X + b0) ----
    {
        float acc[MT0][TT][4];
#pragma unroll
        for (int mt = 0; mt < MT0; mt++) {
            int r0 = warp * MT0 * 16 + mt * 16 + gid;
            float bb0 = b0v[r0], bb1 = b0v[r0 + 8];
#pragma unroll
            for (int t = 0; t < TT; t++) {
                acc[mt][t][0] = bb0; acc[mt][t][1] = bb0;
                acc[mt][t][2] = bb1; acc[mt][t][3] = bb1;
            }
        }
#pragma unroll 1
        for (int ks = 0; ks < K0S; ks++) {
            u32 ah[MT0][4], al[MT0][4];
#pragma unroll
            for (int mt = 0; mt < MT0; mt++) {
                int tile = (warp * MT0 + mt) * K0S + ks;
                uint4 hv = w0h4[tile * 32 + lane];
                ah[mt][0] = hv.x; ah[mt][1] = hv.y; ah[mt][2] = hv.z; ah[mt][3] = hv.w;
                uint4 lv = w0l4[tile * 32 + lane];
                al[mt][0] = lv.x; al[mt][1] = lv.y; al[mt][2] = lv.z; al[mt][3] = lv.w;
            }
#pragma unroll
            for (int t = 0; t < TT; t++) {
                int col = t * 8 + gid;
                int off = col * KP2 + ks * 16 + 2 * tl;
                u32 bh[2], bl[2];
                bh[0] = *(const u32*)(xs_hi + off);
                bh[1] = *(const u32*)(xs_hi + off + 8);
                bl[0] = *(const u32*)(xs_lo + off);
                bl[1] = *(const u32*)(xs_lo + off + 8);
#pragma unroll
                for (int mt = 0; mt < MT0; mt++) {
                    mma_bf16(acc[mt][t], ah[mt], bl);
                    mma_bf16(acc[mt][t], al[mt], bh);
                    mma_bf16(acc[mt][t], ah[mt], bh);
                }
            }
        }
#pragma unroll
        for (int mt = 0; mt < MT0; mt++) {
            int r0 = warp * MT0 * 16 + mt * 16 + gid;
#pragma unroll
            for (int t = 0; t < TT; t++) {
                int c0b = (t * 8 + 2 * tl) * MP2;
                int c1b = c0b + MP2;
                u16 h, l;
                split_bf16(fmaxf(acc[mt][t][0], 0.0f), h, l);
                mid_hi[c0b + r0] = h; mid_lo[c0b + r0] = l;
                split_bf16(fmaxf(acc[mt][t][1], 0.0f), h, l);
                mid_hi[c1b + r0] = h; mid_lo[c1b + r0] = l;
                split_bf16(fmaxf(acc[mt][t][2], 0.0f), h, l);
                mid_hi[c0b + r0 + 8] = h; mid_lo[c0b + r0 + 8] = l;
                split_bf16(fmaxf(acc[mt][t][3], 0.0f), h, l);
                mid_hi[c1b + r0 + 8] = h; mid_lo[c1b + r0 + 8] = l;
            }
        }
    }
    __syncthreads();

    // ---- layer 1 + maxpool ----
    {
        float acc[MT1][TT][4];
#pragma unroll
        for (int mt = 0; mt < MT1; mt++) {
            int r0 = warp * MT1 * 16 + mt * 16 + gid;
            float bb0 = b1v[r0], bb1 = b1v[r0 + 8];
#pragma unroll
            for (int t = 0; t < TT; t++) {
                acc[mt][t][0] = bb0; acc[mt][t][1] = bb0;
                acc[mt][t][2] = bb1; acc[mt][t][3] = bb1;
            }
        }
#pragma unroll 1
        for (int ks = 0; ks < K1S; ks++) {
            u32 ah[MT1][4], al[MT1][4];
#pragma unroll
            for (int mt = 0; mt < MT1; mt++) {
                int tile = (warp * MT1 + mt) * K1S + ks;
                uint4 hv = w1h4[tile * 32 + lane];
                ah[mt][0] = hv.x; ah[mt][1] = hv.y; ah[mt][2] = hv.z; ah[mt][3] = hv.w;
                uint4 lv = w1l4[tile * 32 + lane];
                al[mt][0] = lv.x; al[mt][1] = lv.y; al[mt][2] = lv.z; al[mt][3] = lv.w;
            }
#pragma unroll
            for (int t = 0; t < TT; t++) {
                int col = t * 8 + gid;
                int off = col * MP2 + ks * 16 + 2 * tl;
                u32 bh[2], bl[2];
                bh[0] = *(const u32*)(mid_hi + off);
                bh[1] = *(const u32*)(mid_hi + off + 8);
                bl[0] = *(const u32*)(mid_lo + off);
                bl[1] = *(const u32*)(mid_lo + off + 8);
#pragma unroll
                for (int mt = 0; mt < MT1; mt++) {
                    mma_bf16(acc[mt][t], ah[mt], bl);
                    mma_bf16(acc[mt][t], al[mt], bh);
                    mma_bf16(acc[mt][t], ah[mt], bh);
                }
            }
        }
        // maxpool per group + relu + store
#pragma unroll
        for (int mt = 0; mt < MT1; mt++) {
            int r0 = warp * MT1 * 16 + mt * 16 + gid;
#pragma unroll
            for (int gl = 0; gl < NG; gl++) {
                float m0 = -3.4e38f, m1 = -3.4e38f;
#pragma unroll
                for (int tt = 0; tt < NSG; tt++) {
                    int t = gl * NSG + tt;
                    m0 = fmaxf(m0, fmaxf(acc[mt][t][0], acc[mt][t][1]));
                    m1 = fmaxf(m1, fmaxf(acc[mt][t][2], acc[mt][t][3]));
                }
                m0 = fmaxf(m0, __shfl_xor_sync(0xffffffffu, m0, 1));
                m0 = fmaxf(m0, __shfl_xor_sync(0xffffffffu, m0, 2));
                m1 = fmaxf(m1, __shfl_xor_sync(0xffffffffu, m1, 1));
                m1 = fmaxf(m1, __shfl_xor_sync(0xffffffffu, m1, 2));
                if (tl == 0) {
                    int gs = gs0 + gl;
                    int s  = gs - b * S;
                    float v0 = fmaxf(m0, 0.0f);
                    float v1 = fmaxf(m1, 0.0f);
                    if (FINAL) {
                        out[(size_t)b * C1 * S + (size_t)r0 * S + s]       = v0;
                        out[(size_t)b * C1 * S + (size_t)(r0 + 8) * S + s] = v1;
                    } else {
                        out[(size_t)gs * C1 + r0]     = v0;
                        out[(size_t)gs * C1 + r0 + 8] = v1;
                    }
                }
            }
        }
    }
}

// ---------------------------------------------------------------------------
extern "C" void kernel_launch(void* const* d_in, const int* in_sizes, int n_in,
                              void* d_out, int out_size)
{
    (void)in_sizes; (void)n_in; (void)out_size;
    const float* pc = (const float*)d_in[0];

    float *nx1, *nx2, *nx3, *f1, *f2;
    int* idxb;
    float *w0T, *w1T;
    u16 *w2hi, *w2lo, *w3hi, *w3lo, *w4hi, *w4lo, *w5hi, *w5lo;
    float *b0, *b1, *b2, *b3, *b4, *b5;
    cudaGetSymbolAddress((void**)&nx1, g_nx1);
    cudaGetSymbolAddress((void**)&nx2, g_nx2);
    cudaGetSymbolAddress((void**)&nx3, g_nx3);
    cudaGetSymbolAddress((void**)&idxb, g_idxbuf);
    cudaGetSymbolAddress((void**)&f1, g_f1);
    cudaGetSymbolAddress((void**)&f2, g_f2);
    cudaGetSymbolAddress((void**)&w0T, g_w0T); cudaGetSymbolAddress((void**)&b0, g_b0);
    cudaGetSymbolAddress((void**)&w1T, g_w1T); cudaGetSymbolAddress((void**)&b1, g_b1);
    cudaGetSymbolAddress((void**)&w2hi, g_w2hi); cudaGetSymbolAddress((void**)&w2lo, g_w2lo);
    cudaGetSymbolAddress((void**)&b2, g_b2);
    cudaGetSymbolAddress((void**)&w3hi, g_w3hi); cudaGetSymbolAddress((void**)&w3lo, g_w3lo);
    cudaGetSymbolAddress((void**)&b3, g_b3);
    cudaGetSymbolAddress((void**)&w4hi, g_w4hi); cudaGetSymbolAddress((void**)&w4lo, g_w4lo);
    cudaGetSymbolAddress((void**)&b4, g_b4);
    cudaGetSymbolAddress((void**)&w5hi, g_w5hi); cudaGetSymbolAddress((void**)&w5lo, g_w5lo);
    cudaGetSymbolAddress((void**)&b5, g_b5);

    FoldArgs fa;
    const int cins[6]  = {9, 32, 67, 128, 131, 256};
    const int kps[6]   = {6, 32, 80, 128, 144, 256};
    const int couts[6] = {32, 64, 128, 128, 256, 256};
    u16* wHis[6] = {nullptr, nullptr, w2hi, w3hi, w4hi, w5hi};
    u16* wLos[6] = {nullptr, nullptr, w2lo, w3lo, w4lo, w5lo};
    float* bss[6] = {b0, b1, b2, b3, b4, b5};
    fa.wT[0] = w0T; fa.wT[1] = w1T;
    for (int l = 0; l < 6; l++) {
        fa.w[l]  = (const float*)d_in[1 + 5 * l];
        fa.g[l]  = (const float*)d_in[2 + 5 * l];
        fa.be[l] = (const float*)d_in[3 + 5 * l];
        fa.rm[l] = (const float*)d_in[4 + 5 * l];
        fa.rv[l] = (const float*)d_in[5 + 5 * l];
        fa.wHi[l] = wHis[l]; fa.wLo[l] = wLos[l]; fa.bias[l] = bss[l];
        fa.cin[l] = cins[l]; fa.kp[l] = kps[l]; fa.cout[l] = couts[l];
    }
    fold_all_kernel<<<dim3(72, 6), 256>>>(fa);

    const float rr0 = (float)(0.02 * 0.02);
    const float rr1 = (float)(0.04 * 0.04);
    const float rr2 = (float)(0.08 * 0.08);

    // smem sizes (bytes)
    const int smem0 = ((6 + 32) * 132 + 512) * 4;                     // 22112
    const int smem1 = (32 * 88 * 2 + 32 * 152 * 2) * 2 + 32 * 4;      // 30848
    const int smem2 = (16 * 152 * 2 + 16 * 280 * 2) * 2 + 16 * 4;     // 27712

    auto k0 = sa_mlp0_kernel<6, 32, 64, 32, 4, 128, 8, 16>;
    // stage1: C0=128,C1=128,CF=64,K0P=80,NS=32,SAMP=32,KP2=88,MP2=152
    auto k1 = sa_gemm_kernel<128, 128, 64, 80, 32, 32, 88, 152, false>;
    // stage2: C0=256,C1=256,CF=128,K0P=144,NS=16,SAMP=16,KP2=152,MP2=280
    auto k2 = sa_gemm_kernel<256, 256, 128, 144, 16, 16, 152, 280, true>;

    // ---- stage 0: N=4096 -> S=128 ----
    fps_kernel<4096, 128, 256><<<B, 256>>>(pc, nx1);
    ballquery_kernel<32><<<(B * S0) / 4, 128>>>(nx1, pc, idxb, N0, S0, rr0);
    k0<<<(B * S0) / 4, 128, smem0>>>(pc, nx1, idxb, w0T, b0, w1T, b1, f1, N0, S0);

    // ---- stage 1: N=128 -> S=64 (SAMP=32 -> 64 blocks/batch, 4096 blocks) --
    fps_kernel<128, 64, 128><<<B, 128>>>(nx1, nx2);
    ballquery_kernel<32><<<(B * S1) / 4, 128>>>(nx2, nx1, idxb, S0, S1, rr1);
    k1<<<B * S1, 256, smem1>>>(nx1, f1, nx2, idxb,
                               w2hi, w2lo, b2, w3hi, w3lo, b3, f2, S0, S1);

    // ---- stage 2: N=64 -> S=32 (SAMP=16 -> 32 blocks/batch, 2048 blocks) ---
    fps_kernel<64, 32, 64><<<B, 64>>>(nx2, nx3);
    ballquery_kernel<16><<<(B * S2) / 4, 128>>>(nx3, nx2, idxb, S1, S2, rr2);
    k2<<<B * S2, 256, smem2>>>(nx2, f2, nx3, idxb,
                               w4hi, w4lo, b4, w5hi, w5lo, b5,
                               (float*)d_out, S1, S2);
}